// round 12
// baseline (speedup 1.0000x reference)
#include <cuda_runtime.h>
#include <cuda_bf16.h>
#include <cuda_fp16.h>
#include <cstdint>
#include <math.h>

#define BATCH  2
#define SEQ    2048
#define DMODEL 1024
#define NHEAD  16
#define HDIM   64
#define WIN    256
#define MROWS  (BATCH*SEQ)   /* 4096 */
#define GN     1024
#define KF     1024          /* fp16 GEMM K */

// ---------------- scratch (allocation-free rule: device globals) ----------------
__device__ float g_q [MROWS*DMODEL];
__device__ float g_k [MROWS*DMODEL];
__device__ float g_v [MROWS*DMODEL];

__device__ __half g_xh [(size_t)MROWS*KF];
__device__ __half g_aoh[(size_t)MROWS*KF];
__device__ __half g_wqh[(size_t)DMODEL*KF];
__device__ __half g_wkh[(size_t)DMODEL*KF];
__device__ __half g_wvh[(size_t)DMODEL*KF];
__device__ __half g_woh[(size_t)DMODEL*KF];

// head-major bf16 hi|lo splits for attention: [b, h, s, 128]
__device__ __nv_bfloat16 g_qs[(size_t)MROWS*2*DMODEL];
__device__ __nv_bfloat16 g_ks[(size_t)MROWS*2*DMODEL];
__device__ __nv_bfloat16 g_vs[(size_t)MROWS*2*DMODEL];

// =========================================================================
// common helpers
// =========================================================================
__device__ __forceinline__ uint32_t smem_u32(const void* p) {
    uint32_t a;
    asm("{ .reg .u64 t; cvta.to.shared.u64 t, %1; cvt.u32.u64 %0, t; }"
        : "=r"(a) : "l"(p));
    return a;
}

__device__ __forceinline__ void split4(float4 v, uint2& hi, uint2& lo)
{
    __nv_bfloat162 h01 = __floats2bfloat162_rn(v.x, v.y);
    __nv_bfloat162 h23 = __floats2bfloat162_rn(v.z, v.w);
    __nv_bfloat162 l01 = __floats2bfloat162_rn(v.x - __low2float(h01),
                                               v.y - __high2float(h01));
    __nv_bfloat162 l23 = __floats2bfloat162_rn(v.z - __low2float(h23),
                                               v.w - __high2float(h23));
    hi = make_uint2(*(uint32_t*)&h01, *(uint32_t*)&h23);
    lo = make_uint2(*(uint32_t*)&l01, *(uint32_t*)&l23);
}

#define CP_ASYNC16(dst, src) \
    asm volatile("cp.async.cg.shared.global [%0], [%1], 16;" \
                 :: "r"(dst), "l"(src) : "memory")
#define CP_COMMIT() asm volatile("cp.async.commit_group;" ::: "memory")
#define CP_WAIT1()  asm volatile("cp.async.wait_group 1;"  ::: "memory")
#define CP_WAIT0()  asm volatile("cp.async.wait_group 0;"  ::: "memory")

#define LDMATRIX_X4(r0, r1, r2, r3, addr) \
    asm volatile("ldmatrix.sync.aligned.m8n8.x4.shared.b16 {%0,%1,%2,%3}, [%4];" \
                 : "=r"(r0), "=r"(r1), "=r"(r2), "=r"(r3) : "r"(addr))

#define LDMATRIX_X4_T(r0, r1, r2, r3, addr) \
    asm volatile("ldmatrix.sync.aligned.m8n8.x4.trans.shared.b16 {%0,%1,%2,%3}, [%4];" \
                 : "=r"(r0), "=r"(r1), "=r"(r2), "=r"(r3) : "r"(addr))

// bf16 mma (attention)
#define MMA16816(d, a, b) \
    asm volatile("mma.sync.aligned.m16n8k16.row.col.f32.bf16.bf16.f32 " \
                 "{%0,%1,%2,%3}, {%4,%5,%6,%7}, {%8,%9}, {%0,%1,%2,%3};" \
                 : "+f"((d)[0]), "+f"((d)[1]), "+f"((d)[2]), "+f"((d)[3]) \
                 : "r"((a)[0]), "r"((a)[1]), "r"((a)[2]), "r"((a)[3]), \
                   "r"((b)[0]), "r"((b)[1]))

// fp16 mma (projections)
#define MMAF16(d, a, b) \
    asm volatile("mma.sync.aligned.m16n8k16.row.col.f32.f16.f16.f32 " \
                 "{%0,%1,%2,%3}, {%4,%5,%6,%7}, {%8,%9}, {%0,%1,%2,%3};" \
                 : "+f"((d)[0]), "+f"((d)[1]), "+f"((d)[2]), "+f"((d)[3]) \
                 : "r"((a)[0]), "r"((a)[1]), "r"((a)[2]), "r"((a)[3]), \
                   "r"((b)[0]), "r"((b)[1]))

// =========================================================================
// fp32 -> fp16 converts
// =========================================================================
__global__ __launch_bounds__(256)
void conv_f16(const float* __restrict__ in, __half* __restrict__ out)
{
    size_t i = (size_t)blockIdx.x * 256 + threadIdx.x;
    float4 v = ((const float4*)in)[i];
    __half2 h01 = __floats2half2_rn(v.x, v.y);
    __half2 h23 = __floats2half2_rn(v.z, v.w);
    ((uint2*)out)[i] = make_uint2(*(uint32_t*)&h01, *(uint32_t*)&h23);
}

__global__ __launch_bounds__(256)
void conv_f16x2(const float* __restrict__ in0, const float* __restrict__ in1,
                __half* __restrict__ out0, __half* __restrict__ out1)
{
    const int half_grid = (int)(gridDim.x >> 1);
    const float* in  = (blockIdx.x < half_grid) ? in0 : in1;
    __half* out = (blockIdx.x < half_grid) ? out0 : out1;
    size_t i = (size_t)(blockIdx.x & (half_grid - 1)) * 256 + threadIdx.x;
    float4 v = ((const float4*)in)[i];
    __half2 h01 = __floats2half2_rn(v.x, v.y);
    __half2 h23 = __floats2half2_rn(v.z, v.w);
    ((uint2*)out)[i] = make_uint2(*(uint32_t*)&h01, *(uint32_t*)&h23);
}

// =========================================================================
// q,k,v fp32 -> head-major bf16 hi|lo [b,h,s,128]; Q scaled 1/8
// =========================================================================
__global__ __launch_bounds__(256)
void conv_qkv(const float* __restrict__ q, const float* __restrict__ k,
              const float* __restrict__ v,
              __nv_bfloat16* __restrict__ Qc, __nv_bfloat16* __restrict__ Kc,
              __nv_bfloat16* __restrict__ Vc)
{
    const int r  = blockIdx.x;
    const int c4 = threadIdx.x;
    const int b  = r >> 11;
    const int s  = r & 2047;
    const int h  = c4 >> 4;
    const int d4 = c4 & 15;
    const size_t src = (size_t)r * DMODEL + c4 * 4;
    const size_t dst = ((size_t)(b * NHEAD + h) * SEQ + s) * 128 + d4 * 4;

    uint2 hi, lo;
    float4 t = *(const float4*)(q + src);
    t.x *= 0.125f; t.y *= 0.125f; t.z *= 0.125f; t.w *= 0.125f;
    split4(t, hi, lo);
    *(uint2*)(Qc + dst)      = hi;
    *(uint2*)(Qc + dst + 64) = lo;

    split4(*(const float4*)(k + src), hi, lo);
    *(uint2*)(Kc + dst)      = hi;
    *(uint2*)(Kc + dst + 64) = lo;

    split4(*(const float4*)(v + src), hi, lo);
    *(uint2*)(Vc + dst)      = hi;
    *(uint2*)(Vc + dst + 64) = lo;
}

// =========================================================================
// fp16 GEMM: C[M,1024] = A[M,1024] * B[1024,1024]^T  (fp32 accumulate)
// CTA tile 256x128, 512 threads, 16 warps (4m x 4n), warp tile 64x32.
// BK=32, 3-stage cp.async.  ~110 regs/thread -> 4 warps per SMSP.
// =========================================================================
#define BKT    32
#define NSTG   3
#define NKT    (KF / BKT)            /* 32 */
#define LDK    40
#define A_SB   (256 * LDK * 2)       /* 20480 */
#define B_SB   (128 * LDK * 2)       /* 10240 */
#define STAGE_B (A_SB + B_SB)        /* 30720 */
#define SMEM_GEMM (NSTG * STAGE_B)   /* 92160 */

__device__ __forceinline__
void gemm_f16_body(const __half* __restrict__ A, const __half* __restrict__ B,
                   float* __restrict__ C, char* smem)
{
    const uint32_t sb = smem_u32(smem);

    const int tid  = threadIdx.x;
    const int lane = tid & 31;
    const int wid  = tid >> 5;
    const int wm   = (wid & 3) * 64;     // 4 m-positions
    const int wn   = (wid >> 2) * 32;    // 4 n-positions

    const __half* Ag = A + (size_t)(blockIdx.y * 256) * KF;
    const __half* Bg = B + (size_t)(blockIdx.x * 128) * KF;

    const int cr = tid >> 2;      // 0..127
    const int cc = tid & 3;       // 16B chunk

    const int arow  = ((lane >> 3) & 1) * 8 + (lane & 7);
    const int ahalf = (lane >> 4) * 8;
    const int brow  = ((lane >> 4) << 3) + (lane & 7);
    const int bhalf = ((lane >> 3) & 1) * 8;

    float acc[4][4][4];
    #pragma unroll
    for (int i = 0; i < 4; i++)
        #pragma unroll
        for (int j = 0; j < 4; j++)
            #pragma unroll
            for (int t = 0; t < 4; t++) acc[i][j][t] = 0.f;

    // prologue: stages 0..NSTG-2
    #pragma unroll
    for (int s = 0; s < NSTG - 1; s++) {
        uint32_t sa = sb + s * STAGE_B;
        #pragma unroll
        for (int i = 0; i < 2; i++) {          // A: 1024 chunks / 512 thr
            int r = cr + i * 128;
            CP_ASYNC16(sa + (uint32_t)((r * LDK + cc * 8) * 2),
                       Ag + (size_t)r * KF + s * BKT + cc * 8);
        }
        {                                       // B: 512 chunks / 512 thr
            int r = cr;
            CP_ASYNC16(sa + A_SB + (uint32_t)((r * LDK + cc * 8) * 2),
                       Bg + (size_t)r * KF + s * BKT + cc * 8);
        }
        CP_COMMIT();
    }

    for (int kt = 0; kt < NKT; kt++) {
        CP_WAIT1();
        __syncthreads();

        if (kt + NSTG - 1 < NKT) {
            int s  = (kt + NSTG - 1) % NSTG;
            int kn = kt + NSTG - 1;
            uint32_t sa = sb + s * STAGE_B;
            #pragma unroll
            for (int i = 0; i < 2; i++) {
                int r = cr + i * 128;
                CP_ASYNC16(sa + (uint32_t)((r * LDK + cc * 8) * 2),
                           Ag + (size_t)r * KF + kn * BKT + cc * 8);
            }
            {
                int r = cr;
                CP_ASYNC16(sa + A_SB + (uint32_t)((r * LDK + cc * 8) * 2),
                           Bg + (size_t)r * KF + kn * BKT + cc * 8);
            }
        }
        CP_COMMIT();

        const uint32_t sA = sb + (kt % NSTG) * STAGE_B;
        const uint32_t sB = sA + A_SB;

        #pragma unroll
        for (int kk = 0; kk < 2; kk++) {
            uint32_t afr[4][4];
            uint32_t bfr[4][2];
            #pragma unroll
            for (int mi = 0; mi < 4; mi++) {
                uint32_t addr = sA + (uint32_t)(((wm + mi * 16 + arow) * LDK
                                               + kk * 16 + ahalf) * 2);
                LDMATRIX_X4(afr[mi][0], afr[mi][1], afr[mi][2], afr[mi][3], addr);
            }
            #pragma unroll
            for (int np = 0; np < 2; np++) {
                uint32_t r0, r1, r2, r3;
                uint32_t addr = sB + (uint32_t)(((wn + np * 16 + brow) * LDK
                                               + kk * 16 + bhalf) * 2);
                LDMATRIX_X4(r0, r1, r2, r3, addr);
                bfr[np * 2][0] = r0;  bfr[np * 2][1] = r1;
                bfr[np * 2 + 1][0] = r2;  bfr[np * 2 + 1][1] = r3;
            }
            #pragma unroll
            for (int mi = 0; mi < 4; mi++)
                #pragma unroll
                for (int ni = 0; ni < 4; ni++)
                    MMAF16(acc[mi][ni], afr[mi], bfr[ni]);
        }
    }

    const int g = lane >> 2;
    const int t = lane & 3;
    float* Cb = C + (size_t)(blockIdx.y * 256 + wm) * GN + blockIdx.x * 128 + wn;
    #pragma unroll
    for (int mi = 0; mi < 4; mi++) {
        #pragma unroll
        for (int ni = 0; ni < 4; ni++) {
            float* p = Cb + (size_t)(mi * 16 + g) * GN + ni * 8 + t * 2;
            *(float2*)p            = make_float2(acc[mi][ni][0], acc[mi][ni][1]);
            *(float2*)(p + 8 * GN) = make_float2(acc[mi][ni][2], acc[mi][ni][3]);
        }
    }
}

__global__ __launch_bounds__(512, 1)
void gemm_qkv_f16(const __half* __restrict__ A,
                  const __half* __restrict__ B0, const __half* __restrict__ B1,
                  const __half* __restrict__ B2,
                  float* __restrict__ C0, float* __restrict__ C1,
                  float* __restrict__ C2)
{
    extern __shared__ __align__(128) char smem[];
    const int z = blockIdx.z;
    const __half* B = (z == 0) ? B0 : (z == 1) ? B1 : B2;
    float* C = (z == 0) ? C0 : (z == 1) ? C1 : C2;
    gemm_f16_body(A, B, C, smem);
}

__global__ __launch_bounds__(512, 1)
void gemm_o_f16(const __half* __restrict__ A, const __half* __restrict__ B,
                float* __restrict__ C)
{
    extern __shared__ __align__(128) char smem[];
    gemm_f16_body(A, B, C, smem);
}

// =========================================================================
// Flash sliding-window attention (bf16x3 split); fp16 output.  (unchanged)
// =========================================================================
#define LDA 136
#define SZ_Q  (128 * LDA * 2)
#define SZ_KV (64 * LDA * 2)
#define ATTN_SMEM (SZ_Q + 4 * SZ_KV)

__global__ __launch_bounds__(256, 1)
void attn_mma3(const __nv_bfloat16* __restrict__ Qc,
               const __nv_bfloat16* __restrict__ Kc,
               const __nv_bfloat16* __restrict__ Vc,
               __half* __restrict__ o)
{
    extern __shared__ __align__(128) char smem[];
    const uint32_t sQ  = smem_u32(smem);
    const uint32_t sK0 = sQ + SZ_Q;
    const uint32_t sV0 = sK0 + SZ_KV;
    const uint32_t sK1 = sV0 + SZ_KV;
    const uint32_t sV1 = sK1 + SZ_KV;

    const int b   = blockIdx.z;
    const int h   = blockIdx.y;
    const int q0  = blockIdx.x * 128;
    const int tid = threadIdx.x;
    const int lane = tid & 31;
    const int wid  = tid >> 5;
    const int wm   = wid * 16;

    const __nv_bfloat16* qg = Qc + ((size_t)(b * NHEAD + h) * SEQ + q0) * 128;
    const __nv_bfloat16* kg = Kc + ((size_t)(b * NHEAD + h) * SEQ) * 128;
    const __nv_bfloat16* vg = Vc + ((size_t)(b * NHEAD + h) * SEQ) * 128;

    const int kstart = max(0, q0 - 256);
    const int ntiles = (q0 + 128 - kstart) >> 6;

    #pragma unroll
    for (int i = 0; i < 8; i++) {
        int idx = tid + i * 256;
        int row = idx >> 4;
        int c   = idx & 15;
        CP_ASYNC16(sQ + (uint32_t)(row * (LDA * 2) + c * 16),
                   qg + (size_t)row * 128 + c * 8);
    }
    #pragma unroll
    for (int i = 0; i < 4; i++) {
        int idx = tid + i * 256;
        int row = idx >> 4;
        int c   = idx & 15;
        CP_ASYNC16(sK0 + (uint32_t)(row * (LDA * 2) + c * 16),
                   kg + (size_t)(kstart + row) * 128 + c * 8);
        CP_ASYNC16(sV0 + (uint32_t)(row * (LDA * 2) + c * 16),
                   vg + (size_t)(kstart + row) * 128 + c * 8);
    }
    CP_COMMIT();

    const int g  = lane >> 2;
    const int t4 = lane & 3;
    const int arow  = ((lane >> 3) & 1) * 8 + (lane & 7);
    const int ahalf = (lane >> 4) * 8;
    const int brow  = ((lane >> 4) << 3) + (lane & 7);
    const int bhalf = ((lane >> 3) & 1) * 8;
    const int vrow  = (lane & 7) + ((lane >> 3) & 1) * 8;
    const int vcol  = (lane >> 4) * 8;

    CP_WAIT0();
    __syncthreads();

    uint32_t qf[8][4];
    #pragma unroll
    for (int j = 0; j < 4; j++) {
        LDMATRIX_X4(qf[j][0], qf[j][1], qf[j][2], qf[j][3],
                    sQ + (uint32_t)(((wm + arow) * LDA + j * 16 + ahalf) * 2));
        LDMATRIX_X4(qf[4+j][0], qf[4+j][1], qf[4+j][2], qf[4+j][3],
                    sQ + (uint32_t)(((wm + arow) * LDA + 64 + j * 16 + ahalf) * 2));
    }

    float m0 = -1e30f, m1 = -1e30f, l0 = 0.f, l1 = 0.f;
    float of[8][4];
    #pragma unroll
    for (int i = 0; i < 8; i++)
        #pragma unroll
        for (int j = 0; j < 4; j++) of[i][j] = 0.f;

    const int qrow0 = q0 + wm + g;
    const int qrow1 = qrow0 + 8;

    for (int t = 0; t < ntiles; t++) {
        const int kb = kstart + t * 64;

        if (t + 1 < ntiles) {
            const uint32_t dK = ((t + 1) & 1) ? sK1 : sK0;
            const uint32_t dV = ((t + 1) & 1) ? sV1 : sV0;
            const int kn = kb + 64;
            #pragma unroll
            for (int i = 0; i < 4; i++) {
                int idx = tid + i * 256;
                int row = idx >> 4;
                int c   = idx & 15;
                CP_ASYNC16(dK + (uint32_t)(row * (LDA * 2) + c * 16),
                           kg + (size_t)(kn + row) * 128 + c * 8);
                CP_ASYNC16(dV + (uint32_t)(row * (LDA * 2) + c * 16),
                           vg + (size_t)(kn + row) * 128 + c * 8);
            }
            CP_COMMIT();
        }

        const uint32_t sK = (t & 1) ? sK1 : sK0;
        const uint32_t sV = (t & 1) ? sV1 : sV0;

        const bool active = (kb <= q0 + wm + 15) && (kb + 63 >= q0 + wm - (WIN - 1));

        if (active) {
            float sf[8][4];
            #pragma unroll
            for (int i = 0; i < 8; i++)
                #pragma unroll
                for (int j = 0; j < 4; j++) sf[i][j] = 0.f;

            #pragma unroll
            for (int s = 0; s < 12; s++) {
                const int j = s & 3;
                const uint32_t* af = (s < 8) ? qf[j] : qf[4 + j];
                const int bcol = ((s >= 4 && s < 8) ? 64 : 0) + j * 16;
                #pragma unroll
                for (int np = 0; np < 4; np++) {
                    uint32_t r0, r1, r2, r3;
                    LDMATRIX_X4(r0, r1, r2, r3,
                                sK + (uint32_t)(((np * 16 + brow) * LDA + bcol + bhalf) * 2));
                    uint32_t b01[2] = {r0, r1}, b23[2] = {r2, r3};
                    MMA16816(sf[np * 2],     af, b01);
                    MMA16816(sf[np * 2 + 1], af, b23);
                }
            }

            float tmax0 = -1e30f, tmax1 = -1e30f;
            #pragma unroll
            for (int nt = 0; nt < 8; nt++) {
                int key0 = kb + nt * 8 + t4 * 2;
                int key1 = key0 + 1;
                if (!(key0 <= qrow0 && key0 >= qrow0 - (WIN - 1))) sf[nt][0] = -1e30f;
                if (!(key1 <= qrow0 && key1 >= qrow0 - (WIN - 1))) sf[nt][1] = -1e30f;
                if (!(key0 <= qrow1 && key0 >= qrow1 - (WIN - 1))) sf[nt][2] = -1e30f;
                if (!(key1 <= qrow1 && key1 >= qrow1 - (WIN - 1))) sf[nt][3] = -1e30f;
                tmax0 = fmaxf(tmax0, fmaxf(sf[nt][0], sf[nt][1]));
                tmax1 = fmaxf(tmax1, fmaxf(sf[nt][2], sf[nt][3]));
            }
            tmax0 = fmaxf(tmax0, __shfl_xor_sync(0xffffffffu, tmax0, 1));
            tmax0 = fmaxf(tmax0, __shfl_xor_sync(0xffffffffu, tmax0, 2));
            tmax1 = fmaxf(tmax1, __shfl_xor_sync(0xffffffffu, tmax1, 1));
            tmax1 = fmaxf(tmax1, __shfl_xor_sync(0xffffffffu, tmax1, 2));

            float mn0 = fmaxf(m0, tmax0);
            float mn1 = fmaxf(m1, tmax1);
            float f0 = __expf(m0 - mn0);
            float f1 = __expf(m1 - mn1);
            l0 *= f0; l1 *= f1;
            #pragma unroll
            for (int nt = 0; nt < 8; nt++) {
                of[nt][0] *= f0; of[nt][1] *= f0;
                of[nt][2] *= f1; of[nt][3] *= f1;
            }

            uint32_t phi[8][2], plo[8][2];
            #pragma unroll
            for (int nt = 0; nt < 8; nt++) {
                float p00 = __expf(sf[nt][0] - mn0);
                float p01 = __expf(sf[nt][1] - mn0);
                float p10 = __expf(sf[nt][2] - mn1);
                float p11 = __expf(sf[nt][3] - mn1);
                l0 += p00 + p01;
                l1 += p10 + p11;
                __nv_bfloat162 h0 = __floats2bfloat162_rn(p00, p01);
                __nv_bfloat162 h1 = __floats2bfloat162_rn(p10, p11);
                __nv_bfloat162 e0 = __floats2bfloat162_rn(p00 - __low2float(h0),
                                                          p01 - __high2float(h0));
                __nv_bfloat162 e1 = __floats2bfloat162_rn(p10 - __low2float(h1),
                                                          p11 - __high2float(h1));
                phi[nt][0] = *(uint32_t*)&h0;  phi[nt][1] = *(uint32_t*)&h1;
                plo[nt][0] = *(uint32_t*)&e0;  plo[nt][1] = *(uint32_t*)&e1;
            }
            m0 = mn0; m1 = mn1;

            #pragma unroll
            for (int kj = 0; kj < 4; kj++) {
                uint32_t aPhi[4] = { phi[2*kj][0], phi[2*kj][1],
                                     phi[2*kj+1][0], phi[2*kj+1][1] };
                uint32_t aPlo[4] = { plo[2*kj][0], plo[2*kj][1],
                                     plo[2*kj+1][0], plo[2*kj+1][1] };
                #pragma unroll
                for (int np = 0; np < 4; np++) {
                    uint32_t r0, r1, r2, r3;
                    LDMATRIX_X4_T(r0, r1, r2, r3,
                        sV + (uint32_t)(((kj * 16 + vrow) * LDA + np * 16 + vcol) * 2));
                    {
                        uint32_t b01[2] = {r0, r1}, b23[2] = {r2, r3};
                        MMA16816(of[np * 2],     aPhi, b01);
                        MMA16816(of[np * 2 + 1], aPhi, b23);
                        MMA16816(of[np * 2],     aPlo, b01);
                        MMA16816(of[np * 2 + 1], aPlo, b23);
                    }
                    LDMATRIX_X4_T(r0, r1, r2, r3,
                        sV + (uint32_t)(((kj * 16 + vrow) * LDA + 64 + np * 16 + vcol) * 2));
                    {
                        uint32_t b01[2] = {r0, r1}, b23[2] = {r2, r3};
                        MMA16816(of[np * 2],     aPhi, b01);
                        MMA16816(of[np * 2 + 1], aPhi, b23);
                    }
                }
            }
        }

        if (t + 1 < ntiles) {
            CP_WAIT0();
            __syncthreads();
        }
    }

    l0 += __shfl_xor_sync(0xffffffffu, l0, 1);
    l0 += __shfl_xor_sync(0xffffffffu, l0, 2);
    l1 += __shfl_xor_sync(0xffffffffu, l1, 1);
    l1 += __shfl_xor_sync(0xffffffffu, l1, 2);
    float inv0 = 1.f / l0;
    float inv1 = 1.f / l1;

    __half* ob = o + (size_t)(b * SEQ + q0 + wm) * DMODEL + h * HDIM;
    #pragma unroll
    for (int nt = 0; nt < 8; nt++) {
        int col = nt * 8 + t4 * 2;
        __half2 v0 = __floats2half2_rn(of[nt][0] * inv0, of[nt][1] * inv0);
        __half2 v1 = __floats2half2_rn(of[nt][2] * inv1, of[nt][3] * inv1);
        *(__half2*)(ob + (size_t)g * DMODEL + col)       = v0;
        *(__half2*)(ob + (size_t)(g + 8) * DMODEL + col) = v1;
    }
}

// ---------------------------------------------------------------------------
extern "C" void kernel_launch(void* const* d_in, const int* in_sizes, int n_in,
                              void* d_out, int out_size)
{
    const float* x  = (const float*)d_in[0];
    const float* Wq = (const float*)d_in[1];
    const float* Wk = (const float*)d_in[2];
    const float* Wv = (const float*)d_in[3];
    const float* Wo = (const float*)d_in[4];
    float* out = (float*)d_out;

    float *qp, *kp, *vp;
    __half *xh, *aoh, *wqh, *wkh, *wvh, *woh;
    __nv_bfloat16 *qs, *ks, *vs;
    cudaGetSymbolAddress((void**)&qp,  g_q);
    cudaGetSymbolAddress((void**)&kp,  g_k);
    cudaGetSymbolAddress((void**)&vp,  g_v);
    cudaGetSymbolAddress((void**)&xh,  g_xh);
    cudaGetSymbolAddress((void**)&aoh, g_aoh);
    cudaGetSymbolAddress((void**)&wqh, g_wqh);
    cudaGetSymbolAddress((void**)&wkh, g_wkh);
    cudaGetSymbolAddress((void**)&wvh, g_wvh);
    cudaGetSymbolAddress((void**)&woh, g_woh);
    cudaGetSymbolAddress((void**)&qs,  g_qs);
    cudaGetSymbolAddress((void**)&ks,  g_ks);
    cudaGetSymbolAddress((void**)&vs,  g_vs);

    cudaFuncSetAttribute(gemm_qkv_f16, cudaFuncAttributeMaxDynamicSharedMemorySize,
                         SMEM_GEMM);
    cudaFuncSetAttribute(gemm_o_f16, cudaFuncAttributeMaxDynamicSharedMemorySize,
                         SMEM_GEMM);
    cudaFuncSetAttribute(attn_mma3, cudaFuncAttributeMaxDynamicSharedMemorySize,
                         ATTN_SMEM);

    // 0: x -> fp16
    conv_f16<<<4096, 256>>>(x, xh);
    // 1-2: weights -> fp16
    conv_f16x2<<<2048, 256>>>(Wq, Wk, wqh, wkh);
    conv_f16x2<<<2048, 256>>>(Wv, Wo, wvh, woh);
    // 3: batched QKV projection, 512-thread CTAs (profiled slot)
    gemm_qkv_f16<<<dim3(GN / 128, MROWS / 256, 3), 512, SMEM_GEMM>>>(
        xh, wqh, wkh, wvh, qp, kp, vp);
    // 4: attention input splits
    conv_qkv<<<MROWS, 256>>>(qp, kp, vp, qs, ks, vs);
    // 5: attention
    attn_mma3<<<dim3(SEQ / 128, NHEAD, BATCH), 256, ATTN_SMEM>>>(qs, ks, vs, aoh);
    // 6: output projection
    gemm_o_f16<<<dim3(GN / 128, MROWS / 256), 512, SMEM_GEMM>>>(aoh, woh, out);
}

// round 14
// speedup vs baseline: 1.2176x; 1.2176x over previous
#include <cuda_runtime.h>
#include <cuda_bf16.h>
#include <cuda_fp16.h>
#include <cstdint>
#include <math.h>

#define BATCH  2
#define SEQ    2048
#define DMODEL 1024
#define NHEAD  16
#define HDIM   64
#define WIN    256
#define MROWS  (BATCH*SEQ)   /* 4096 */
#define GN     1024
#define KF     1024          /* fp16 GEMM K */

// ---------------- scratch (allocation-free rule: device globals) ----------------
__device__ float g_q [MROWS*DMODEL];
__device__ float g_k [MROWS*DMODEL];
__device__ float g_v [MROWS*DMODEL];

__device__ __half g_xh [(size_t)MROWS*KF];
__device__ __half g_aoh[(size_t)MROWS*KF];
__device__ __half g_wqh[(size_t)DMODEL*KF];
__device__ __half g_wkh[(size_t)DMODEL*KF];
__device__ __half g_wvh[(size_t)DMODEL*KF];
__device__ __half g_woh[(size_t)DMODEL*KF];

// head-major fp16 for attention: [b, h, s, 64]
__device__ __half g_qs[(size_t)MROWS*DMODEL];
__device__ __half g_ks[(size_t)MROWS*DMODEL];
__device__ __half g_vs[(size_t)MROWS*DMODEL];

// =========================================================================
// common helpers
// =========================================================================
__device__ __forceinline__ uint32_t smem_u32(const void* p) {
    uint32_t a;
    asm("{ .reg .u64 t; cvta.to.shared.u64 t, %1; cvt.u32.u64 %0, t; }"
        : "=r"(a) : "l"(p));
    return a;
}

#define CP_ASYNC16(dst, src) \
    asm volatile("cp.async.cg.shared.global [%0], [%1], 16;" \
                 :: "r"(dst), "l"(src) : "memory")
#define CP_COMMIT() asm volatile("cp.async.commit_group;" ::: "memory")
#define CP_WAIT1()  asm volatile("cp.async.wait_group 1;"  ::: "memory")
#define CP_WAIT0()  asm volatile("cp.async.wait_group 0;"  ::: "memory")

#define LDMATRIX_X4(r0, r1, r2, r3, addr) \
    asm volatile("ldmatrix.sync.aligned.m8n8.x4.shared.b16 {%0,%1,%2,%3}, [%4];" \
                 : "=r"(r0), "=r"(r1), "=r"(r2), "=r"(r3) : "r"(addr))

#define LDMATRIX_X4_T(r0, r1, r2, r3, addr) \
    asm volatile("ldmatrix.sync.aligned.m8n8.x4.trans.shared.b16 {%0,%1,%2,%3}, [%4];" \
                 : "=r"(r0), "=r"(r1), "=r"(r2), "=r"(r3) : "r"(addr))

// fp16 mma (projections + attention)
#define MMAF16(d, a, b) \
    asm volatile("mma.sync.aligned.m16n8k16.row.col.f32.f16.f16.f32 " \
                 "{%0,%1,%2,%3}, {%4,%5,%6,%7}, {%8,%9}, {%0,%1,%2,%3};" \
                 : "+f"((d)[0]), "+f"((d)[1]), "+f"((d)[2]), "+f"((d)[3]) \
                 : "r"((a)[0]), "r"((a)[1]), "r"((a)[2]), "r"((a)[3]), \
                   "r"((b)[0]), "r"((b)[1]))

// =========================================================================
// fused fp32 -> fp16 convert: x (4096 rows) then Wq,Wk,Wv,Wo (1024 rows each)
// =========================================================================
__global__ __launch_bounds__(256)
void conv_in_f16(const float* __restrict__ x,
                 const float* __restrict__ Wq, const float* __restrict__ Wk,
                 const float* __restrict__ Wv, const float* __restrict__ Wo,
                 __half* __restrict__ xh,
                 __half* __restrict__ wqh, __half* __restrict__ wkh,
                 __half* __restrict__ wvh, __half* __restrict__ woh)
{
    const int bid = blockIdx.x;
    const float* in;
    __half* out;
    int r;
    if (bid < MROWS) { in = x; out = xh; r = bid; }
    else {
        int m = (bid - MROWS) >> 10;
        r = (bid - MROWS) & 1023;
        in  = (m == 0) ? Wq : (m == 1) ? Wk : (m == 2) ? Wv : Wo;
        out = (m == 0) ? wqh : (m == 1) ? wkh : (m == 2) ? wvh : woh;
    }
    size_t i = (size_t)r * 256 + threadIdx.x;
    float4 v = ((const float4*)in)[i];
    __half2 h01 = __floats2half2_rn(v.x, v.y);
    __half2 h23 = __floats2half2_rn(v.z, v.w);
    ((uint2*)out)[i] = make_uint2(*(uint32_t*)&h01, *(uint32_t*)&h23);
}

// =========================================================================
// q,k,v fp32 -> head-major fp16 [b,h,s,64]; Q scaled 1/8
// =========================================================================
__global__ __launch_bounds__(256)
void conv_qkv(const float* __restrict__ q, const float* __restrict__ k,
              const float* __restrict__ v,
              __half* __restrict__ Qc, __half* __restrict__ Kc,
              __half* __restrict__ Vc)
{
    const int r  = blockIdx.x;
    const int c4 = threadIdx.x;
    const int b  = r >> 11;
    const int s  = r & 2047;
    const int h  = c4 >> 4;
    const int d4 = c4 & 15;
    const size_t src = (size_t)r * DMODEL + c4 * 4;
    const size_t dst = ((size_t)(b * NHEAD + h) * SEQ + s) * 64 + d4 * 4;

    float4 t = *(const float4*)(q + src);
    __half2 q01 = __floats2half2_rn(t.x * 0.125f, t.y * 0.125f);
    __half2 q23 = __floats2half2_rn(t.z * 0.125f, t.w * 0.125f);
    *(uint2*)(Qc + dst) = make_uint2(*(uint32_t*)&q01, *(uint32_t*)&q23);

    t = *(const float4*)(k + src);
    __half2 k01 = __floats2half2_rn(t.x, t.y);
    __half2 k23 = __floats2half2_rn(t.z, t.w);
    *(uint2*)(Kc + dst) = make_uint2(*(uint32_t*)&k01, *(uint32_t*)&k23);

    t = *(const float4*)(v + src);
    __half2 v01 = __floats2half2_rn(t.x, t.y);
    __half2 v23 = __floats2half2_rn(t.z, t.w);
    *(uint2*)(Vc + dst) = make_uint2(*(uint32_t*)&v01, *(uint32_t*)&v23);
}

// =========================================================================
// fp16 GEMM: C[M,1024] = A[M,1024] * B[1024,1024]^T  (fp32 accumulate)
// CTA tile 128x256, warp tile 64x64 (8 warps, 2x4), BK=32, 3-stage cp.async.
// (R11 config — at the mma.sync issue ceiling; unchanged)
// =========================================================================
#define BKT    32
#define NSTG   3
#define NKT    (KF / BKT)            /* 32 */
#define LDK    40
#define A_SB   (128 * LDK * 2)       /* 10240 */
#define B_SB   (256 * LDK * 2)       /* 20480 */
#define STAGE_B (A_SB + B_SB)        /* 30720 */
#define SMEM_GEMM (NSTG * STAGE_B)   /* 92160 */

__device__ __forceinline__
void gemm_f16_body(const __half* __restrict__ A, const __half* __restrict__ B,
                   float* __restrict__ C, char* smem)
{
    const uint32_t sb = smem_u32(smem);

    const int tid  = threadIdx.x;
    const int lane = tid & 31;
    const int wid  = tid >> 5;
    const int wm   = (wid & 1) * 64;
    const int wn   = (wid >> 1) * 64;

    const __half* Ag = A + (size_t)(blockIdx.y * 128) * KF;
    const __half* Bg = B + (size_t)(blockIdx.x * 256) * KF;

    const int cr = tid >> 2;
    const int cc = tid & 3;

    const int arow  = ((lane >> 3) & 1) * 8 + (lane & 7);
    const int ahalf = (lane >> 4) * 8;
    const int brow  = ((lane >> 4) << 3) + (lane & 7);
    const int bhalf = ((lane >> 3) & 1) * 8;

    float acc[4][8][4];
    #pragma unroll
    for (int i = 0; i < 4; i++)
        #pragma unroll
        for (int j = 0; j < 8; j++)
            #pragma unroll
            for (int t = 0; t < 4; t++) acc[i][j][t] = 0.f;

    #pragma unroll
    for (int s = 0; s < NSTG - 1; s++) {
        uint32_t sa = sb + s * STAGE_B;
        #pragma unroll
        for (int i = 0; i < 2; i++) {
            int r = cr + i * 64;
            CP_ASYNC16(sa + (uint32_t)((r * LDK + cc * 8) * 2),
                       Ag + (size_t)r * KF + s * BKT + cc * 8);
        }
        #pragma unroll
        for (int i = 0; i < 4; i++) {
            int r = cr + i * 64;
            CP_ASYNC16(sa + A_SB + (uint32_t)((r * LDK + cc * 8) * 2),
                       Bg + (size_t)r * KF + s * BKT + cc * 8);
        }
        CP_COMMIT();
    }

    for (int kt = 0; kt < NKT; kt++) {
        CP_WAIT1();
        __syncthreads();

        if (kt + NSTG - 1 < NKT) {
            int s  = (kt + NSTG - 1) % NSTG;
            int kn = kt + NSTG - 1;
            uint32_t sa = sb + s * STAGE_B;
            #pragma unroll
            for (int i = 0; i < 2; i++) {
                int r = cr + i * 64;
                CP_ASYNC16(sa + (uint32_t)((r * LDK + cc * 8) * 2),
                           Ag + (size_t)r * KF + kn * BKT + cc * 8);
            }
            #pragma unroll
            for (int i = 0; i < 4; i++) {
                int r = cr + i * 64;
                CP_ASYNC16(sa + A_SB + (uint32_t)((r * LDK + cc * 8) * 2),
                           Bg + (size_t)r * KF + kn * BKT + cc * 8);
            }
        }
        CP_COMMIT();

        const uint32_t sA = sb + (kt % NSTG) * STAGE_B;
        const uint32_t sB = sA + A_SB;

        #pragma unroll
        for (int kk = 0; kk < 2; kk++) {
            uint32_t afr[4][4];
            uint32_t bfr[8][2];
            #pragma unroll
            for (int mi = 0; mi < 4; mi++) {
                uint32_t addr = sA + (uint32_t)(((wm + mi * 16 + arow) * LDK
                                               + kk * 16 + ahalf) * 2);
                LDMATRIX_X4(afr[mi][0], afr[mi][1], afr[mi][2], afr[mi][3], addr);
            }
            #pragma unroll
            for (int np = 0; np < 4; np++) {
                uint32_t r0, r1, r2, r3;
                uint32_t addr = sB + (uint32_t)(((wn + np * 16 + brow) * LDK
                                               + kk * 16 + bhalf) * 2);
                LDMATRIX_X4(r0, r1, r2, r3, addr);
                bfr[np * 2][0] = r0;  bfr[np * 2][1] = r1;
                bfr[np * 2 + 1][0] = r2;  bfr[np * 2 + 1][1] = r3;
            }
            #pragma unroll
            for (int mi = 0; mi < 4; mi++)
                #pragma unroll
                for (int ni = 0; ni < 8; ni++)
                    MMAF16(acc[mi][ni], afr[mi], bfr[ni]);
        }
    }

    const int g = lane >> 2;
    const int t = lane & 3;
    float* Cb = C + (size_t)(blockIdx.y * 128 + wm) * GN + blockIdx.x * 256 + wn;
    #pragma unroll
    for (int mi = 0; mi < 4; mi++) {
        #pragma unroll
        for (int ni = 0; ni < 8; ni++) {
            float* p = Cb + (size_t)(mi * 16 + g) * GN + ni * 8 + t * 2;
            *(float2*)p            = make_float2(acc[mi][ni][0], acc[mi][ni][1]);
            *(float2*)(p + 8 * GN) = make_float2(acc[mi][ni][2], acc[mi][ni][3]);
        }
    }
}

__global__ __launch_bounds__(256, 1)
void gemm_qkv_f16(const __half* __restrict__ A,
                  const __half* __restrict__ B0, const __half* __restrict__ B1,
                  const __half* __restrict__ B2,
                  float* __restrict__ C0, float* __restrict__ C1,
                  float* __restrict__ C2)
{
    extern __shared__ __align__(128) char smem[];
    const int z = blockIdx.z;
    const __half* B = (z == 0) ? B0 : (z == 1) ? B1 : B2;
    float* C = (z == 0) ? C0 : (z == 1) ? C1 : C2;
    gemm_f16_body(A, B, C, smem);
}

__global__ __launch_bounds__(256, 1)
void gemm_o_f16(const __half* __restrict__ A, const __half* __restrict__ B,
                float* __restrict__ C)
{
    extern __shared__ __align__(128) char smem[];
    gemm_f16_body(A, B, C, smem);
}

// =========================================================================
// Flash sliding-window attention, single-pass fp16 (3x fewer MMAs than bf16x3).
// 8 warps x 16 query rows (BQ=128), cp.async double-buffered K/V, fp16 out.
// =========================================================================
#define LDA 72                         /* fp16 row stride: 144B */
#define SZ_Q  (128 * LDA * 2)          /* 18432 */
#define SZ_KV (64 * LDA * 2)           /* 9216  */
#define ATTN_SMEM (SZ_Q + 4 * SZ_KV)   /* 55296 */

__global__ __launch_bounds__(256, 2)
void attn_f16(const __half* __restrict__ Qc, const __half* __restrict__ Kc,
              const __half* __restrict__ Vc, __half* __restrict__ o)
{
    extern __shared__ __align__(128) char smem[];
    const uint32_t sQ  = smem_u32(smem);
    const uint32_t sK0 = sQ + SZ_Q;
    const uint32_t sV0 = sK0 + SZ_KV;
    const uint32_t sK1 = sV0 + SZ_KV;
    const uint32_t sV1 = sK1 + SZ_KV;

    const int b   = blockIdx.z;
    const int h   = blockIdx.y;
    const int q0  = blockIdx.x * 128;
    const int tid = threadIdx.x;
    const int lane = tid & 31;
    const int wid  = tid >> 5;
    const int wm   = wid * 16;

    const __half* qg = Qc + ((size_t)(b * NHEAD + h) * SEQ + q0) * 64;
    const __half* kg = Kc + ((size_t)(b * NHEAD + h) * SEQ) * 64;
    const __half* vg = Vc + ((size_t)(b * NHEAD + h) * SEQ) * 64;

    const int kstart = max(0, q0 - 256);
    const int ntiles = (q0 + 128 - kstart) >> 6;

    // ---- prologue: Q tile (128x64) + KV tile 0 (64x64 each) ----
    #pragma unroll
    for (int i = 0; i < 4; i++) {
        int idx = tid + i * 256;         // 0..1023
        int row = idx >> 3;
        int c   = idx & 7;
        CP_ASYNC16(sQ + (uint32_t)(row * (LDA * 2) + c * 16),
                   qg + (size_t)row * 64 + c * 8);
    }
    #pragma unroll
    for (int i = 0; i < 2; i++) {
        int idx = tid + i * 256;         // 0..511
        int row = idx >> 3;
        int c   = idx & 7;
        CP_ASYNC16(sK0 + (uint32_t)(row * (LDA * 2) + c * 16),
                   kg + (size_t)(kstart + row) * 64 + c * 8);
        CP_ASYNC16(sV0 + (uint32_t)(row * (LDA * 2) + c * 16),
                   vg + (size_t)(kstart + row) * 64 + c * 8);
    }
    CP_COMMIT();

    const int g  = lane >> 2;
    const int t4 = lane & 3;
    const int arow  = ((lane >> 3) & 1) * 8 + (lane & 7);
    const int ahalf = (lane >> 4) * 8;
    const int brow  = ((lane >> 4) << 3) + (lane & 7);
    const int bhalf = ((lane >> 3) & 1) * 8;
    const int vrow  = (lane & 7) + ((lane >> 3) & 1) * 8;
    const int vcol  = (lane >> 4) * 8;

    CP_WAIT0();
    __syncthreads();    // Q, K0, V0 resident

    // ---- hoist Q fragments (4 x k16 segments) ----
    uint32_t qf[4][4];
    #pragma unroll
    for (int j = 0; j < 4; j++)
        LDMATRIX_X4(qf[j][0], qf[j][1], qf[j][2], qf[j][3],
                    sQ + (uint32_t)(((wm + arow) * LDA + j * 16 + ahalf) * 2));

    float m0 = -1e30f, m1 = -1e30f, l0 = 0.f, l1 = 0.f;
    float of[8][4];
    #pragma unroll
    for (int i = 0; i < 8; i++)
        #pragma unroll
        for (int j = 0; j < 4; j++) of[i][j] = 0.f;

    const int qrow0 = q0 + wm + g;
    const int qrow1 = qrow0 + 8;

    for (int t = 0; t < ntiles; t++) {
        const int kb = kstart + t * 64;

        // prefetch next tile
        if (t + 1 < ntiles) {
            const uint32_t dK = ((t + 1) & 1) ? sK1 : sK0;
            const uint32_t dV = ((t + 1) & 1) ? sV1 : sV0;
            const int kn = kb + 64;
            #pragma unroll
            for (int i = 0; i < 2; i++) {
                int idx = tid + i * 256;
                int row = idx >> 3;
                int c   = idx & 7;
                CP_ASYNC16(dK + (uint32_t)(row * (LDA * 2) + c * 16),
                           kg + (size_t)(kn + row) * 64 + c * 8);
                CP_ASYNC16(dV + (uint32_t)(row * (LDA * 2) + c * 16),
                           vg + (size_t)(kn + row) * 64 + c * 8);
            }
            CP_COMMIT();
        }

        const uint32_t sK = (t & 1) ? sK1 : sK0;
        const uint32_t sV = (t & 1) ? sV1 : sV0;

        const bool active = (kb <= q0 + wm + 15) && (kb + 63 >= q0 + wm - (WIN - 1));

        if (active) {
            // ---- S = Q K^T : 4 k16 steps ----
            float sf[8][4];
            #pragma unroll
            for (int i = 0; i < 8; i++)
                #pragma unroll
                for (int j = 0; j < 4; j++) sf[i][j] = 0.f;

            #pragma unroll
            for (int j = 0; j < 4; j++) {
                #pragma unroll
                for (int np = 0; np < 4; np++) {
                    uint32_t r0, r1, r2, r3;
                    LDMATRIX_X4(r0, r1, r2, r3,
                                sK + (uint32_t)(((np * 16 + brow) * LDA + j * 16 + bhalf) * 2));
                    uint32_t b01[2] = {r0, r1}, b23[2] = {r2, r3};
                    MMAF16(sf[np * 2],     qf[j], b01);
                    MMAF16(sf[np * 2 + 1], qf[j], b23);
                }
            }

            // ---- mask + online softmax ----
            float tmax0 = -1e30f, tmax1 = -1e30f;
            #pragma unroll
            for (int nt = 0; nt < 8; nt++) {
                int key0 = kb + nt * 8 + t4 * 2;
                int key1 = key0 + 1;
                if (!(key0 <= qrow0 && key0 >= qrow0 - (WIN - 1))) sf[nt][0] = -1e30f;
                if (!(key1 <= qrow0 && key1 >= qrow0 - (WIN - 1))) sf[nt][1] = -1e30f;
                if (!(key0 <= qrow1 && key0 >= qrow1 - (WIN - 1))) sf[nt][2] = -1e30f;
                if (!(key1 <= qrow1 && key1 >= qrow1 - (WIN - 1))) sf[nt][3] = -1e30f;
                tmax0 = fmaxf(tmax0, fmaxf(sf[nt][0], sf[nt][1]));
                tmax1 = fmaxf(tmax1, fmaxf(sf[nt][2], sf[nt][3]));
            }
            tmax0 = fmaxf(tmax0, __shfl_xor_sync(0xffffffffu, tmax0, 1));
            tmax0 = fmaxf(tmax0, __shfl_xor_sync(0xffffffffu, tmax0, 2));
            tmax1 = fmaxf(tmax1, __shfl_xor_sync(0xffffffffu, tmax1, 1));
            tmax1 = fmaxf(tmax1, __shfl_xor_sync(0xffffffffu, tmax1, 2));

            float mn0 = fmaxf(m0, tmax0);
            float mn1 = fmaxf(m1, tmax1);
            float f0 = __expf(m0 - mn0);
            float f1 = __expf(m1 - mn1);
            l0 *= f0; l1 *= f1;
            #pragma unroll
            for (int nt = 0; nt < 8; nt++) {
                of[nt][0] *= f0; of[nt][1] *= f0;
                of[nt][2] *= f1; of[nt][3] *= f1;
            }

            uint32_t phi[8][2];
            #pragma unroll
            for (int nt = 0; nt < 8; nt++) {
                float p00 = __expf(sf[nt][0] - mn0);
                float p01 = __expf(sf[nt][1] - mn0);
                float p10 = __expf(sf[nt][2] - mn1);
                float p11 = __expf(sf[nt][3] - mn1);
                l0 += p00 + p01;
                l1 += p10 + p11;
                __half2 h0 = __floats2half2_rn(p00, p01);
                __half2 h1 = __floats2half2_rn(p10, p11);
                phi[nt][0] = *(uint32_t*)&h0;
                phi[nt][1] = *(uint32_t*)&h1;
            }
            m0 = mn0; m1 = mn1;

            // ---- O += P V  (single fp16 pass) ----
            #pragma unroll
            for (int kj = 0; kj < 4; kj++) {
                uint32_t aP[4] = { phi[2*kj][0], phi[2*kj][1],
                                   phi[2*kj+1][0], phi[2*kj+1][1] };
                #pragma unroll
                for (int np = 0; np < 4; np++) {
                    uint32_t r0, r1, r2, r3;
                    LDMATRIX_X4_T(r0, r1, r2, r3,
                        sV + (uint32_t)(((kj * 16 + vrow) * LDA + np * 16 + vcol) * 2));
                    uint32_t b01[2] = {r0, r1}, b23[2] = {r2, r3};
                    MMAF16(of[np * 2],     aP, b01);
                    MMAF16(of[np * 2 + 1], aP, b23);
                }
            }
        }

        if (t + 1 < ntiles) {
            CP_WAIT0();
            __syncthreads();
        }
    }

    // ---- finalize ----
    l0 += __shfl_xor_sync(0xffffffffu, l0, 1);
    l0 += __shfl_xor_sync(0xffffffffu, l0, 2);
    l1 += __shfl_xor_sync(0xffffffffu, l1, 1);
    l1 += __shfl_xor_sync(0xffffffffu, l1, 2);
    float inv0 = 1.f / l0;
    float inv1 = 1.f / l1;

    __half* ob = o + (size_t)(b * SEQ + q0 + wm) * DMODEL + h * HDIM;
    #pragma unroll
    for (int nt = 0; nt < 8; nt++) {
        int col = nt * 8 + t4 * 2;
        __half2 v0 = __floats2half2_rn(of[nt][0] * inv0, of[nt][1] * inv0);
        __half2 v1 = __floats2half2_rn(of[nt][2] * inv1, of[nt][3] * inv1);
        *(__half2*)(ob + (size_t)g * DMODEL + col)       = v0;
        *(__half2*)(ob + (size_t)(g + 8) * DMODEL + col) = v1;
    }
}

// ---------------------------------------------------------------------------
extern "C" void kernel_launch(void* const* d_in, const int* in_sizes, int n_in,
                              void* d_out, int out_size)
{
    const float* x  = (const float*)d_in[0];
    const float* Wq = (const float*)d_in[1];
    const float* Wk = (const float*)d_in[2];
    const float* Wv = (const float*)d_in[3];
    const float* Wo = (const float*)d_in[4];
    float* out = (float*)d_out;

    float *qp, *kp, *vp;
    __half *xh, *aoh, *wqh, *wkh, *wvh, *woh, *qs, *ks, *vs;
    cudaGetSymbolAddress((void**)&qp,  g_q);
    cudaGetSymbolAddress((void**)&kp,  g_k);
    cudaGetSymbolAddress((void**)&vp,  g_v);
    cudaGetSymbolAddress((void**)&xh,  g_xh);
    cudaGetSymbolAddress((void**)&aoh, g_aoh);
    cudaGetSymbolAddress((void**)&wqh, g_wqh);
    cudaGetSymbolAddress((void**)&wkh, g_wkh);
    cudaGetSymbolAddress((void**)&wvh, g_wvh);
    cudaGetSymbolAddress((void**)&woh, g_woh);
    cudaGetSymbolAddress((void**)&qs,  g_qs);
    cudaGetSymbolAddress((void**)&ks,  g_ks);
    cudaGetSymbolAddress((void**)&vs,  g_vs);

    cudaFuncSetAttribute(gemm_qkv_f16, cudaFuncAttributeMaxDynamicSharedMemorySize,
                         SMEM_GEMM);
    cudaFuncSetAttribute(gemm_o_f16, cudaFuncAttributeMaxDynamicSharedMemorySize,
                         SMEM_GEMM);
    cudaFuncSetAttribute(attn_f16, cudaFuncAttributeMaxDynamicSharedMemorySize,
                         ATTN_SMEM);

    // 0: all input converts (x + 4 weights)
    conv_in_f16<<<MROWS + 4 * 1024, 256>>>(x, Wq, Wk, Wv, Wo,
                                           xh, wqh, wkh, wvh, woh);
    // 1: batched QKV projection
    gemm_qkv_f16<<<dim3(GN / 256, MROWS / 128, 3), 256, SMEM_GEMM>>>(
        xh, wqh, wkh, wvh, qp, kp, vp);
    // 2: attention input repack (fp16 head-major)
    conv_qkv<<<MROWS, 256>>>(qp, kp, vp, qs, ks, vs);
    // 3: attention, single-pass fp16 (profiled slot)
    attn_f16<<<dim3(SEQ / 128, NHEAD, BATCH), 256, ATTN_SMEM>>>(qs, ks, vs, aoh);
    // 4: output projection
    gemm_o_f16<<<dim3(GN / 256, MROWS / 128), 256, SMEM_GEMM>>>(aoh, woh, out);
}

// round 15
// speedup vs baseline: 1.2889x; 1.0585x over previous
#include <cuda_runtime.h>
#include <cuda_bf16.h>
#include <cuda_fp16.h>
#include <cstdint>
#include <math.h>

#define BATCH  2
#define SEQ    2048
#define DMODEL 1024
#define NHEAD  16
#define HDIM   64
#define WIN    256
#define MROWS  (BATCH*SEQ)   /* 4096 */
#define GN     1024
#define KF     1024          /* fp16 GEMM K */

// ---------------- scratch (allocation-free rule: device globals) ----------------
__device__ __half g_xh [(size_t)MROWS*KF];
__device__ __half g_aoh[(size_t)MROWS*KF];
__device__ __half g_wqh[(size_t)DMODEL*KF];
__device__ __half g_wkh[(size_t)DMODEL*KF];
__device__ __half g_wvh[(size_t)DMODEL*KF];
__device__ __half g_woh[(size_t)DMODEL*KF];

// head-major fp16 for attention: [b, h, s, 64]
__device__ __half g_qs[(size_t)MROWS*DMODEL];
__device__ __half g_ks[(size_t)MROWS*DMODEL];
__device__ __half g_vs[(size_t)MROWS*DMODEL];

// =========================================================================
// common helpers
// =========================================================================
__device__ __forceinline__ uint32_t smem_u32(const void* p) {
    uint32_t a;
    asm("{ .reg .u64 t; cvta.to.shared.u64 t, %1; cvt.u32.u64 %0, t; }"
        : "=r"(a) : "l"(p));
    return a;
}

#define CP_ASYNC16(dst, src) \
    asm volatile("cp.async.cg.shared.global [%0], [%1], 16;" \
                 :: "r"(dst), "l"(src) : "memory")
#define CP_COMMIT() asm volatile("cp.async.commit_group;" ::: "memory")
#define CP_WAIT1()  asm volatile("cp.async.wait_group 1;"  ::: "memory")
#define CP_WAIT0()  asm volatile("cp.async.wait_group 0;"  ::: "memory")

#define LDMATRIX_X4(r0, r1, r2, r3, addr) \
    asm volatile("ldmatrix.sync.aligned.m8n8.x4.shared.b16 {%0,%1,%2,%3}, [%4];" \
                 : "=r"(r0), "=r"(r1), "=r"(r2), "=r"(r3) : "r"(addr))

#define LDMATRIX_X4_T(r0, r1, r2, r3, addr) \
    asm volatile("ldmatrix.sync.aligned.m8n8.x4.trans.shared.b16 {%0,%1,%2,%3}, [%4];" \
                 : "=r"(r0), "=r"(r1), "=r"(r2), "=r"(r3) : "r"(addr))

#define MMAF16(d, a, b) \
    asm volatile("mma.sync.aligned.m16n8k16.row.col.f32.f16.f16.f32 " \
                 "{%0,%1,%2,%3}, {%4,%5,%6,%7}, {%8,%9}, {%0,%1,%2,%3};" \
                 : "+f"((d)[0]), "+f"((d)[1]), "+f"((d)[2]), "+f"((d)[3]) \
                 : "r"((a)[0]), "r"((a)[1]), "r"((a)[2]), "r"((a)[3]), \
                   "r"((b)[0]), "r"((b)[1]))

// =========================================================================
// fused fp32 -> fp16 convert: x (4096 rows) then Wq,Wk,Wv,Wo (1024 rows each)
// =========================================================================
__global__ __launch_bounds__(256)
void conv_in_f16(const float* __restrict__ x,
                 const float* __restrict__ Wq, const float* __restrict__ Wk,
                 const float* __restrict__ Wv, const float* __restrict__ Wo,
                 __half* __restrict__ xh,
                 __half* __restrict__ wqh, __half* __restrict__ wkh,
                 __half* __restrict__ wvh, __half* __restrict__ woh)
{
    const int bid = blockIdx.x;
    const float* in;
    __half* out;
    int r;
    if (bid < MROWS) { in = x; out = xh; r = bid; }
    else {
        int m = (bid - MROWS) >> 10;
        r = (bid - MROWS) & 1023;
        in  = (m == 0) ? Wq : (m == 1) ? Wk : (m == 2) ? Wv : Wo;
        out = (m == 0) ? wqh : (m == 1) ? wkh : (m == 2) ? wvh : woh;
    }
    size_t i = (size_t)r * 256 + threadIdx.x;
    float4 v = ((const float4*)in)[i];
    __half2 h01 = __floats2half2_rn(v.x, v.y);
    __half2 h23 = __floats2half2_rn(v.z, v.w);
    ((uint2*)out)[i] = make_uint2(*(uint32_t*)&h01, *(uint32_t*)&h23);
}

// =========================================================================
// fp16 GEMM body: CTA tile 128x256, warp tile 64x64 (8 warps), BK=32,
// 3-stage cp.async.  MODE 0: fp32 row-major C.  MODE 1: fp16 head-major
// [b,h,s,64] output with scale (QKV path; warp's 64 cols = one head).
// =========================================================================
#define BKT    32
#define NSTG   3
#define NKT    (KF / BKT)            /* 32 */
#define LDK    40
#define A_SB   (128 * LDK * 2)       /* 10240 */
#define B_SB   (256 * LDK * 2)       /* 20480 */
#define STAGE_B (A_SB + B_SB)        /* 30720 */
#define SMEM_GEMM (NSTG * STAGE_B)   /* 92160 */

template<int MODE>
__device__ __forceinline__
void gemm_f16_body(const __half* __restrict__ A, const __half* __restrict__ B,
                   float* __restrict__ C, __half* __restrict__ Ch,
                   float scale, char* smem)
{
    const uint32_t sb = smem_u32(smem);

    const int tid  = threadIdx.x;
    const int lane = tid & 31;
    const int wid  = tid >> 5;
    const int wm   = (wid & 1) * 64;
    const int wn   = (wid >> 1) * 64;

    const __half* Ag = A + (size_t)(blockIdx.y * 128) * KF;
    const __half* Bg = B + (size_t)(blockIdx.x * 256) * KF;

    const int cr = tid >> 2;
    const int cc = tid & 3;

    const int arow  = ((lane >> 3) & 1) * 8 + (lane & 7);
    const int ahalf = (lane >> 4) * 8;
    const int brow  = ((lane >> 4) << 3) + (lane & 7);
    const int bhalf = ((lane >> 3) & 1) * 8;

    float acc[4][8][4];
    #pragma unroll
    for (int i = 0; i < 4; i++)
        #pragma unroll
        for (int j = 0; j < 8; j++)
            #pragma unroll
            for (int t = 0; t < 4; t++) acc[i][j][t] = 0.f;

    #pragma unroll
    for (int s = 0; s < NSTG - 1; s++) {
        uint32_t sa = sb + s * STAGE_B;
        #pragma unroll
        for (int i = 0; i < 2; i++) {
            int r = cr + i * 64;
            CP_ASYNC16(sa + (uint32_t)((r * LDK + cc * 8) * 2),
                       Ag + (size_t)r * KF + s * BKT + cc * 8);
        }
        #pragma unroll
        for (int i = 0; i < 4; i++) {
            int r = cr + i * 64;
            CP_ASYNC16(sa + A_SB + (uint32_t)((r * LDK + cc * 8) * 2),
                       Bg + (size_t)r * KF + s * BKT + cc * 8);
        }
        CP_COMMIT();
    }

    for (int kt = 0; kt < NKT; kt++) {
        CP_WAIT1();
        __syncthreads();

        if (kt + NSTG - 1 < NKT) {
            int s  = (kt + NSTG - 1) % NSTG;
            int kn = kt + NSTG - 1;
            uint32_t sa = sb + s * STAGE_B;
            #pragma unroll
            for (int i = 0; i < 2; i++) {
                int r = cr + i * 64;
                CP_ASYNC16(sa + (uint32_t)((r * LDK + cc * 8) * 2),
                           Ag + (size_t)r * KF + kn * BKT + cc * 8);
            }
            #pragma unroll
            for (int i = 0; i < 4; i++) {
                int r = cr + i * 64;
                CP_ASYNC16(sa + A_SB + (uint32_t)((r * LDK + cc * 8) * 2),
                           Bg + (size_t)r * KF + kn * BKT + cc * 8);
            }
        }
        CP_COMMIT();

        const uint32_t sA = sb + (kt % NSTG) * STAGE_B;
        const uint32_t sB = sA + A_SB;

        #pragma unroll
        for (int kk = 0; kk < 2; kk++) {
            uint32_t afr[4][4];
            uint32_t bfr[8][2];
            #pragma unroll
            for (int mi = 0; mi < 4; mi++) {
                uint32_t addr = sA + (uint32_t)(((wm + mi * 16 + arow) * LDK
                                               + kk * 16 + ahalf) * 2);
                LDMATRIX_X4(afr[mi][0], afr[mi][1], afr[mi][2], afr[mi][3], addr);
            }
            #pragma unroll
            for (int np = 0; np < 4; np++) {
                uint32_t r0, r1, r2, r3;
                uint32_t addr = sB + (uint32_t)(((wn + np * 16 + brow) * LDK
                                               + kk * 16 + bhalf) * 2);
                LDMATRIX_X4(r0, r1, r2, r3, addr);
                bfr[np * 2][0] = r0;  bfr[np * 2][1] = r1;
                bfr[np * 2 + 1][0] = r2;  bfr[np * 2 + 1][1] = r3;
            }
            #pragma unroll
            for (int mi = 0; mi < 4; mi++)
                #pragma unroll
                for (int ni = 0; ni < 8; ni++)
                    MMAF16(acc[mi][ni], afr[mi], bfr[ni]);
        }
    }

    const int g = lane >> 2;
    const int t = lane & 3;

    if (MODE == 0) {
        float* Cb = C + (size_t)(blockIdx.y * 128 + wm) * GN + blockIdx.x * 256 + wn;
        #pragma unroll
        for (int mi = 0; mi < 4; mi++) {
            #pragma unroll
            for (int ni = 0; ni < 8; ni++) {
                float* p = Cb + (size_t)(mi * 16 + g) * GN + ni * 8 + t * 2;
                *(float2*)p            = make_float2(acc[mi][ni][0], acc[mi][ni][1]);
                *(float2*)(p + 8 * GN) = make_float2(acc[mi][ni][2], acc[mi][ni][3]);
            }
        }
    } else {
        // fp16 head-major [b,h,s,64]: this warp's 64 cols = head h
        const int h = blockIdx.x * 4 + (wid >> 1);
        #pragma unroll
        for (int mi = 0; mi < 4; mi++) {
            int row0 = blockIdx.y * 128 + wm + mi * 16 + g;   // b*SEQ + s
            #pragma unroll
            for (int half = 0; half < 2; half++) {
                int row = row0 + half * 8;
                int b   = row >> 11;
                int s   = row & 2047;
                __half* dst = Ch + ((size_t)(b * NHEAD + h) * SEQ + s) * 64;
                #pragma unroll
                for (int ni = 0; ni < 8; ni++) {
                    __half2 v = __floats2half2_rn(acc[mi][ni][half * 2] * scale,
                                                  acc[mi][ni][half * 2 + 1] * scale);
                    *(__half2*)(dst + ni * 8 + t * 2) = v;
                }
            }
        }
    }
}

__global__ __launch_bounds__(256, 1)
void gemm_qkv_f16(const __half* __restrict__ A,
                  const __half* __restrict__ B0, const __half* __restrict__ B1,
                  const __half* __restrict__ B2,
                  __half* __restrict__ Q, __half* __restrict__ K,
                  __half* __restrict__ V)
{
    extern __shared__ __align__(128) char smem[];
    const int z = blockIdx.z;
    const __half* B = (z == 0) ? B0 : (z == 1) ? B1 : B2;
    __half* Ch = (z == 0) ? Q : (z == 1) ? K : V;
    float scale = (z == 0) ? 0.125f : 1.f;
    gemm_f16_body<1>(A, B, nullptr, Ch, scale, smem);
}

__global__ __launch_bounds__(256, 1)
void gemm_o_f16(const __half* __restrict__ A, const __half* __restrict__ B,
                float* __restrict__ C)
{
    extern __shared__ __align__(128) char smem[];
    gemm_f16_body<0>(A, B, C, nullptr, 1.f, smem);
}

// =========================================================================
// Flash sliding-window attention, single-pass fp16; warp-uniform mask skip.
// 8 warps x 16 query rows (BQ=128), cp.async double-buffered K/V, fp16 out.
// =========================================================================
#define LDA 72                         /* fp16 row stride: 144B */
#define SZ_Q  (128 * LDA * 2)          /* 18432 */
#define SZ_KV (64 * LDA * 2)           /* 9216  */
#define ATTN_SMEM (SZ_Q + 4 * SZ_KV)   /* 55296 */

__global__ __launch_bounds__(256, 2)
void attn_f16(const __half* __restrict__ Qc, const __half* __restrict__ Kc,
              const __half* __restrict__ Vc, __half* __restrict__ o)
{
    extern __shared__ __align__(128) char smem[];
    const uint32_t sQ  = smem_u32(smem);
    const uint32_t sK0 = sQ + SZ_Q;
    const uint32_t sV0 = sK0 + SZ_KV;
    const uint32_t sK1 = sV0 + SZ_KV;
    const uint32_t sV1 = sK1 + SZ_KV;

    const int b   = blockIdx.z;
    const int h   = blockIdx.y;
    const int q0  = blockIdx.x * 128;
    const int tid = threadIdx.x;
    const int lane = tid & 31;
    const int wid  = tid >> 5;
    const int wm   = wid * 16;

    const __half* qg = Qc + ((size_t)(b * NHEAD + h) * SEQ + q0) * 64;
    const __half* kg = Kc + ((size_t)(b * NHEAD + h) * SEQ) * 64;
    const __half* vg = Vc + ((size_t)(b * NHEAD + h) * SEQ) * 64;

    const int kstart = max(0, q0 - 256);
    const int ntiles = (q0 + 128 - kstart) >> 6;

    #pragma unroll
    for (int i = 0; i < 4; i++) {
        int idx = tid + i * 256;
        int row = idx >> 3;
        int c   = idx & 7;
        CP_ASYNC16(sQ + (uint32_t)(row * (LDA * 2) + c * 16),
                   qg + (size_t)row * 64 + c * 8);
    }
    #pragma unroll
    for (int i = 0; i < 2; i++) {
        int idx = tid + i * 256;
        int row = idx >> 3;
        int c   = idx & 7;
        CP_ASYNC16(sK0 + (uint32_t)(row * (LDA * 2) + c * 16),
                   kg + (size_t)(kstart + row) * 64 + c * 8);
        CP_ASYNC16(sV0 + (uint32_t)(row * (LDA * 2) + c * 16),
                   vg + (size_t)(kstart + row) * 64 + c * 8);
    }
    CP_COMMIT();

    const int g  = lane >> 2;
    const int t4 = lane & 3;
    const int arow  = ((lane >> 3) & 1) * 8 + (lane & 7);
    const int ahalf = (lane >> 4) * 8;
    const int brow  = ((lane >> 4) << 3) + (lane & 7);
    const int bhalf = ((lane >> 3) & 1) * 8;
    const int vrow  = (lane & 7) + ((lane >> 3) & 1) * 8;
    const int vcol  = (lane >> 4) * 8;

    CP_WAIT0();
    __syncthreads();

    uint32_t qf[4][4];
    #pragma unroll
    for (int j = 0; j < 4; j++)
        LDMATRIX_X4(qf[j][0], qf[j][1], qf[j][2], qf[j][3],
                    sQ + (uint32_t)(((wm + arow) * LDA + j * 16 + ahalf) * 2));

    float m0 = -1e30f, m1 = -1e30f, l0 = 0.f, l1 = 0.f;
    float of[8][4];
    #pragma unroll
    for (int i = 0; i < 8; i++)
        #pragma unroll
        for (int j = 0; j < 4; j++) of[i][j] = 0.f;

    const int qrow0 = q0 + wm + g;
    const int qrow1 = qrow0 + 8;

    for (int t = 0; t < ntiles; t++) {
        const int kb = kstart + t * 64;

        if (t + 1 < ntiles) {
            const uint32_t dK = ((t + 1) & 1) ? sK1 : sK0;
            const uint32_t dV = ((t + 1) & 1) ? sV1 : sV0;
            const int kn = kb + 64;
            #pragma unroll
            for (int i = 0; i < 2; i++) {
                int idx = tid + i * 256;
                int row = idx >> 3;
                int c   = idx & 7;
                CP_ASYNC16(dK + (uint32_t)(row * (LDA * 2) + c * 16),
                           kg + (size_t)(kn + row) * 64 + c * 8);
                CP_ASYNC16(dV + (uint32_t)(row * (LDA * 2) + c * 16),
                           vg + (size_t)(kn + row) * 64 + c * 8);
            }
            CP_COMMIT();
        }

        const uint32_t sK = (t & 1) ? sK1 : sK0;
        const uint32_t sV = (t & 1) ? sV1 : sV0;

        const bool active = (kb <= q0 + wm + 15) && (kb + 63 >= q0 + wm - (WIN - 1));

        if (active) {
            float sf[8][4];
            #pragma unroll
            for (int i = 0; i < 8; i++)
                #pragma unroll
                for (int j = 0; j < 4; j++) sf[i][j] = 0.f;

            #pragma unroll
            for (int j = 0; j < 4; j++) {
                #pragma unroll
                for (int np = 0; np < 4; np++) {
                    uint32_t r0, r1, r2, r3;
                    LDMATRIX_X4(r0, r1, r2, r3,
                                sK + (uint32_t)(((np * 16 + brow) * LDA + j * 16 + bhalf) * 2));
                    uint32_t b01[2] = {r0, r1}, b23[2] = {r2, r3};
                    MMAF16(sf[np * 2],     qf[j], b01);
                    MMAF16(sf[np * 2 + 1], qf[j], b23);
                }
            }

            // warp-uniform: tile fully inside every row's window?
            const bool full = (kb + 63 <= q0 + wm) &&
                              (kb >= q0 + wm + 15 - (WIN - 1));
            if (!full) {
                #pragma unroll
                for (int nt = 0; nt < 8; nt++) {
                    int key0 = kb + nt * 8 + t4 * 2;
                    int key1 = key0 + 1;
                    if (!(key0 <= qrow0 && key0 >= qrow0 - (WIN - 1))) sf[nt][0] = -1e30f;
                    if (!(key1 <= qrow0 && key1 >= qrow0 - (WIN - 1))) sf[nt][1] = -1e30f;
                    if (!(key0 <= qrow1 && key0 >= qrow1 - (WIN - 1))) sf[nt][2] = -1e30f;
                    if (!(key1 <= qrow1 && key1 >= qrow1 - (WIN - 1))) sf[nt][3] = -1e30f;
                }
            }

            float tmax0 = -1e30f, tmax1 = -1e30f;
            #pragma unroll
            for (int nt = 0; nt < 8; nt++) {
                tmax0 = fmaxf(tmax0, fmaxf(sf[nt][0], sf[nt][1]));
                tmax1 = fmaxf(tmax1, fmaxf(sf[nt][2], sf[nt][3]));
            }
            tmax0 = fmaxf(tmax0, __shfl_xor_sync(0xffffffffu, tmax0, 1));
            tmax0 = fmaxf(tmax0, __shfl_xor_sync(0xffffffffu, tmax0, 2));
            tmax1 = fmaxf(tmax1, __shfl_xor_sync(0xffffffffu, tmax1, 1));
            tmax1 = fmaxf(tmax1, __shfl_xor_sync(0xffffffffu, tmax1, 2));

            float mn0 = fmaxf(m0, tmax0);
            float mn1 = fmaxf(m1, tmax1);
            float f0 = __expf(m0 - mn0);
            float f1 = __expf(m1 - mn1);
            l0 *= f0; l1 *= f1;
            #pragma unroll
            for (int nt = 0; nt < 8; nt++) {
                of[nt][0] *= f0; of[nt][1] *= f0;
                of[nt][2] *= f1; of[nt][3] *= f1;
            }

            uint32_t phi[8][2];
            #pragma unroll
            for (int nt = 0; nt < 8; nt++) {
                float p00 = __expf(sf[nt][0] - mn0);
                float p01 = __expf(sf[nt][1] - mn0);
                float p10 = __expf(sf[nt][2] - mn1);
                float p11 = __expf(sf[nt][3] - mn1);
                l0 += p00 + p01;
                l1 += p10 + p11;
                __half2 h0 = __floats2half2_rn(p00, p01);
                __half2 h1 = __floats2half2_rn(p10, p11);
                phi[nt][0] = *(uint32_t*)&h0;
                phi[nt][1] = *(uint32_t*)&h1;
            }
            m0 = mn0; m1 = mn1;

            #pragma unroll
            for (int kj = 0; kj < 4; kj++) {
                uint32_t aP[4] = { phi[2*kj][0], phi[2*kj][1],
                                   phi[2*kj+1][0], phi[2*kj+1][1] };
                #pragma unroll
                for (int np = 0; np < 4; np++) {
                    uint32_t r0, r1, r2, r3;
                    LDMATRIX_X4_T(r0, r1, r2, r3,
                        sV + (uint32_t)(((kj * 16 + vrow) * LDA + np * 16 + vcol) * 2));
                    uint32_t b01[2] = {r0, r1}, b23[2] = {r2, r3};
                    MMAF16(of[np * 2],     aP, b01);
                    MMAF16(of[np * 2 + 1], aP, b23);
                }
            }
        }

        if (t + 1 < ntiles) {
            CP_WAIT0();
            __syncthreads();
        }
    }

    l0 += __shfl_xor_sync(0xffffffffu, l0, 1);
    l0 += __shfl_xor_sync(0xffffffffu, l0, 2);
    l1 += __shfl_xor_sync(0xffffffffu, l1, 1);
    l1 += __shfl_xor_sync(0xffffffffu, l1, 2);
    float inv0 = 1.f / l0;
    float inv1 = 1.f / l1;

    __half* ob = o + (size_t)(b * SEQ + q0 + wm) * DMODEL + h * HDIM;
    #pragma unroll
    for (int nt = 0; nt < 8; nt++) {
        int col = nt * 8 + t4 * 2;
        __half2 v0 = __floats2half2_rn(of[nt][0] * inv0, of[nt][1] * inv0);
        __half2 v1 = __floats2half2_rn(of[nt][2] * inv1, of[nt][3] * inv1);
        *(__half2*)(ob + (size_t)g * DMODEL + col)       = v0;
        *(__half2*)(ob + (size_t)(g + 8) * DMODEL + col) = v1;
    }
}

// ---------------------------------------------------------------------------
extern "C" void kernel_launch(void* const* d_in, const int* in_sizes, int n_in,
                              void* d_out, int out_size)
{
    const float* x  = (const float*)d_in[0];
    const float* Wq = (const float*)d_in[1];
    const float* Wk = (const float*)d_in[2];
    const float* Wv = (const float*)d_in[3];
    const float* Wo = (const float*)d_in[4];
    float* out = (float*)d_out;

    __half *xh, *aoh, *wqh, *wkh, *wvh, *woh, *qs, *ks, *vs;
    cudaGetSymbolAddress((void**)&xh,  g_xh);
    cudaGetSymbolAddress((void**)&aoh, g_aoh);
    cudaGetSymbolAddress((void**)&wqh, g_wqh);
    cudaGetSymbolAddress((void**)&wkh, g_wkh);
    cudaGetSymbolAddress((void**)&wvh, g_wvh);
    cudaGetSymbolAddress((void**)&woh, g_woh);
    cudaGetSymbolAddress((void**)&qs,  g_qs);
    cudaGetSymbolAddress((void**)&ks,  g_ks);
    cudaGetSymbolAddress((void**)&vs,  g_vs);

    cudaFuncSetAttribute(gemm_qkv_f16, cudaFuncAttributeMaxDynamicSharedMemorySize,
                         SMEM_GEMM);
    cudaFuncSetAttribute(gemm_o_f16, cudaFuncAttributeMaxDynamicSharedMemorySize,
                         SMEM_GEMM);
    cudaFuncSetAttribute(attn_f16, cudaFuncAttributeMaxDynamicSharedMemorySize,
                         ATTN_SMEM);

    // 0: all input converts (x + 4 weights)
    conv_in_f16<<<MROWS + 4 * 1024, 256>>>(x, Wq, Wk, Wv, Wo,
                                           xh, wqh, wkh, wvh, woh);
    // 1: batched QKV projection, fused fp16 head-major epilogue
    gemm_qkv_f16<<<dim3(GN / 256, MROWS / 128, 3), 256, SMEM_GEMM>>>(
        xh, wqh, wkh, wvh, qs, ks, vs);
    // 2: attention, single-pass fp16
    attn_f16<<<dim3(SEQ / 128, NHEAD, BATCH), 256, ATTN_SMEM>>>(qs, ks, vs, aoh);
    // 3: output projection (profiled slot)
    gemm_o_f16<<<dim3(GN / 256, MROWS / 128), 256, SMEM_GEMM>>>(aoh, woh, out);
}

// round 17
// speedup vs baseline: 1.4472x; 1.1228x over previous
#include <cuda_runtime.h>
#include <cuda_bf16.h>
#include <cuda_fp16.h>
#include <cstdint>
#include <math.h>

#define BATCH  2
#define SEQ    2048
#define DMODEL 1024
#define NHEAD  16
#define HDIM   64
#define WIN    256
#define MROWS  (BATCH*SEQ)   /* 4096 */
#define GN     1024
#define KF     1024          /* fp16 GEMM K */

// ---------------- scratch (allocation-free rule: device globals) ----------------
__device__ __half g_xh [(size_t)MROWS*KF];
__device__ __half g_aoh[(size_t)MROWS*KF];
__device__ __half g_wqh[(size_t)DMODEL*KF];
__device__ __half g_wkh[(size_t)DMODEL*KF];
__device__ __half g_wvh[(size_t)DMODEL*KF];
__device__ __half g_woh[(size_t)DMODEL*KF];

// head-major fp16 for attention: [b, h, s, 64]
__device__ __half g_qs[(size_t)MROWS*DMODEL];
__device__ __half g_ks[(size_t)MROWS*DMODEL];
__device__ __half g_vs[(size_t)MROWS*DMODEL];

// =========================================================================
// common helpers
// =========================================================================
__device__ __forceinline__ uint32_t smem_u32(const void* p) {
    uint32_t a;
    asm("{ .reg .u64 t; cvta.to.shared.u64 t, %1; cvt.u32.u64 %0, t; }"
        : "=r"(a) : "l"(p));
    return a;
}

__device__ __forceinline__ float ex2(float x) {
    float r;
    asm("ex2.approx.ftz.f32 %0, %1;" : "=f"(r) : "f"(x));
    return r;
}

#define CP_ASYNC16(dst, src) \
    asm volatile("cp.async.cg.shared.global [%0], [%1], 16;" \
                 :: "r"(dst), "l"(src) : "memory")
#define CP_COMMIT() asm volatile("cp.async.commit_group;" ::: "memory")
#define CP_WAIT0()  asm volatile("cp.async.wait_group 0;"  ::: "memory")

#define LDMATRIX_X4(r0, r1, r2, r3, addr) \
    asm volatile("ldmatrix.sync.aligned.m8n8.x4.shared.b16 {%0,%1,%2,%3}, [%4];" \
                 : "=r"(r0), "=r"(r1), "=r"(r2), "=r"(r3) : "r"(addr))

#define LDMATRIX_X4_T(r0, r1, r2, r3, addr) \
    asm volatile("ldmatrix.sync.aligned.m8n8.x4.trans.shared.b16 {%0,%1,%2,%3}, [%4];" \
                 : "=r"(r0), "=r"(r1), "=r"(r2), "=r"(r3) : "r"(addr))

#define MMAF16(d, a, b) \
    asm volatile("mma.sync.aligned.m16n8k16.row.col.f32.f16.f16.f32 " \
                 "{%0,%1,%2,%3}, {%4,%5,%6,%7}, {%8,%9}, {%0,%1,%2,%3};" \
                 : "+f"((d)[0]), "+f"((d)[1]), "+f"((d)[2]), "+f"((d)[3]) \
                 : "r"((a)[0]), "r"((a)[1]), "r"((a)[2]), "r"((a)[3]), \
                   "r"((b)[0]), "r"((b)[1]))

// =========================================================================
// fused fp32 -> fp16 convert: x (4096 rows) then Wq,Wk,Wv,Wo (1024 rows each)
// =========================================================================
__global__ __launch_bounds__(256)
void conv_in_f16(const float* __restrict__ x,
                 const float* __restrict__ Wq, const float* __restrict__ Wk,
                 const float* __restrict__ Wv, const float* __restrict__ Wo,
                 __half* __restrict__ xh,
                 __half* __restrict__ wqh, __half* __restrict__ wkh,
                 __half* __restrict__ wvh, __half* __restrict__ woh)
{
    const int bid = blockIdx.x;
    const float* in;
    __half* out;
    int r;
    if (bid < MROWS) { in = x; out = xh; r = bid; }
    else {
        int m = (bid - MROWS) >> 10;
        r = (bid - MROWS) & 1023;
        in  = (m == 0) ? Wq : (m == 1) ? Wk : (m == 2) ? Wv : Wo;
        out = (m == 0) ? wqh : (m == 1) ? wkh : (m == 2) ? wvh : woh;
    }
    size_t i = (size_t)r * 256 + threadIdx.x;
    float4 v = ((const float4*)in)[i];
    __half2 h01 = __floats2half2_rn(v.x, v.y);
    __half2 h23 = __floats2half2_rn(v.z, v.w);
    ((uint2*)out)[i] = make_uint2(*(uint32_t*)&h01, *(uint32_t*)&h23);
}

// =========================================================================
// fp16 GEMM body: CTA tile 128x256, warp tile 64x64 (8 warps), BK=64,
// 2-stage cp.async (fewer barriers per K).  MODE 0: fp32 row-major C.
// MODE 1: fp16 head-major [b,h,s,64] output with scale (QKV path).
// =========================================================================
#define BKT    64
#define NSTG   2
#define NKT    (KF / BKT)            /* 16 */
#define LDK    72                    /* 64 + 8 pad halfs; 144B row stride */
#define A_SB   (128 * LDK * 2)       /* 18432 */
#define B_SB   (256 * LDK * 2)       /* 36864 */
#define STAGE_B (A_SB + B_SB)        /* 55296 */
#define SMEM_GEMM (NSTG * STAGE_B)   /* 110592 */

template<int MODE>
__device__ __forceinline__
void gemm_f16_body(const __half* __restrict__ A, const __half* __restrict__ B,
                   float* __restrict__ C, __half* __restrict__ Ch,
                   float scale, char* smem)
{
    const uint32_t sb = smem_u32(smem);

    const int tid  = threadIdx.x;
    const int lane = tid & 31;
    const int wid  = tid >> 5;
    const int wm   = (wid & 1) * 64;
    const int wn   = (wid >> 1) * 64;

    const __half* Ag = A + (size_t)(blockIdx.y * 128) * KF;
    const __half* Bg = B + (size_t)(blockIdx.x * 256) * KF;

    const int cr8 = tid >> 3;     // 0..31
    const int cc8 = tid & 7;      // 16B chunk within 64-half row

    const int arow  = ((lane >> 3) & 1) * 8 + (lane & 7);
    const int ahalf = (lane >> 4) * 8;
    const int brow  = ((lane >> 4) << 3) + (lane & 7);
    const int bhalf = ((lane >> 3) & 1) * 8;

    float acc[4][8][4];
    #pragma unroll
    for (int i = 0; i < 4; i++)
        #pragma unroll
        for (int j = 0; j < 8; j++)
            #pragma unroll
            for (int t = 0; t < 4; t++) acc[i][j][t] = 0.f;

    // prologue: stage 0
    {
        uint32_t sa = sb;
        #pragma unroll
        for (int i = 0; i < 4; i++) {          // A: 1024 chunks
            int row = cr8 + i * 32;
            CP_ASYNC16(sa + (uint32_t)((row * LDK + cc8 * 8) * 2),
                       Ag + (size_t)row * KF + cc8 * 8);
        }
        #pragma unroll
        for (int i = 0; i < 8; i++) {          // B: 2048 chunks
            int row = cr8 + i * 32;
            CP_ASYNC16(sa + A_SB + (uint32_t)((row * LDK + cc8 * 8) * 2),
                       Bg + (size_t)row * KF + cc8 * 8);
        }
        CP_COMMIT();
    }

    for (int kt = 0; kt < NKT; kt++) {
        CP_WAIT0();
        __syncthreads();

        if (kt + 1 < NKT) {
            uint32_t sa = sb + ((kt + 1) & 1) * STAGE_B;
            int kn = (kt + 1) * BKT;
            #pragma unroll
            for (int i = 0; i < 4; i++) {
                int row = cr8 + i * 32;
                CP_ASYNC16(sa + (uint32_t)((row * LDK + cc8 * 8) * 2),
                           Ag + (size_t)row * KF + kn + cc8 * 8);
            }
            #pragma unroll
            for (int i = 0; i < 8; i++) {
                int row = cr8 + i * 32;
                CP_ASYNC16(sa + A_SB + (uint32_t)((row * LDK + cc8 * 8) * 2),
                           Bg + (size_t)row * KF + kn + cc8 * 8);
            }
            CP_COMMIT();
        }

        const uint32_t sA = sb + (kt & 1) * STAGE_B;
        const uint32_t sB = sA + A_SB;

        #pragma unroll
        for (int kk = 0; kk < 4; kk++) {
            uint32_t afr[4][4];
            uint32_t bfr[8][2];
            #pragma unroll
            for (int mi = 0; mi < 4; mi++) {
                uint32_t addr = sA + (uint32_t)(((wm + mi * 16 + arow) * LDK
                                               + kk * 16 + ahalf) * 2);
                LDMATRIX_X4(afr[mi][0], afr[mi][1], afr[mi][2], afr[mi][3], addr);
            }
            #pragma unroll
            for (int np = 0; np < 4; np++) {
                uint32_t r0, r1, r2, r3;
                uint32_t addr = sB + (uint32_t)(((wn + np * 16 + brow) * LDK
                                               + kk * 16 + bhalf) * 2);
                LDMATRIX_X4(r0, r1, r2, r3, addr);
                bfr[np * 2][0] = r0;  bfr[np * 2][1] = r1;
                bfr[np * 2 + 1][0] = r2;  bfr[np * 2 + 1][1] = r3;
            }
            #pragma unroll
            for (int mi = 0; mi < 4; mi++)
                #pragma unroll
                for (int ni = 0; ni < 8; ni++)
                    MMAF16(acc[mi][ni], afr[mi], bfr[ni]);
        }
    }

    const int g = lane >> 2;
    const int t = lane & 3;

    if (MODE == 0) {
        float* Cb = C + (size_t)(blockIdx.y * 128 + wm) * GN + blockIdx.x * 256 + wn;
        #pragma unroll
        for (int mi = 0; mi < 4; mi++) {
            #pragma unroll
            for (int ni = 0; ni < 8; ni++) {
                float* p = Cb + (size_t)(mi * 16 + g) * GN + ni * 8 + t * 2;
                *(float2*)p            = make_float2(acc[mi][ni][0], acc[mi][ni][1]);
                *(float2*)(p + 8 * GN) = make_float2(acc[mi][ni][2], acc[mi][ni][3]);
            }
        }
    } else {
        // fp16 head-major [b,h,s,64]: this warp's 64 cols = head h
        const int h = blockIdx.x * 4 + (wid >> 1);
        #pragma unroll
        for (int mi = 0; mi < 4; mi++) {
            int row0 = blockIdx.y * 128 + wm + mi * 16 + g;
            #pragma unroll
            for (int half = 0; half < 2; half++) {
                int row = row0 + half * 8;
                int b   = row >> 11;
                int s   = row & 2047;
                __half* dst = Ch + ((size_t)(b * NHEAD + h) * SEQ + s) * 64;
                #pragma unroll
                for (int ni = 0; ni < 8; ni++) {
                    __half2 v = __floats2half2_rn(acc[mi][ni][half * 2] * scale,
                                                  acc[mi][ni][half * 2 + 1] * scale);
                    *(__half2*)(dst + ni * 8 + t * 2) = v;
                }
            }
        }
    }
}

__global__ __launch_bounds__(256, 1)
void gemm_qkv_f16(const __half* __restrict__ A,
                  const __half* __restrict__ B0, const __half* __restrict__ B1,
                  const __half* __restrict__ B2,
                  __half* __restrict__ Q, __half* __restrict__ K,
                  __half* __restrict__ V)
{
    extern __shared__ __align__(128) char smem[];
    const int z = blockIdx.z;
    const __half* B = (z == 0) ? B0 : (z == 1) ? B1 : B2;
    __half* Ch = (z == 0) ? Q : (z == 1) ? K : V;
    // Q pre-scaled by 1/8 * log2(e) so attention scores live in log2 domain
    float scale = (z == 0) ? 0.125f * 1.4426950408889634f : 1.f;
    gemm_f16_body<1>(A, B, nullptr, Ch, scale, smem);
}

__global__ __launch_bounds__(256, 1)
void gemm_o_f16(const __half* __restrict__ A, const __half* __restrict__ B,
                float* __restrict__ C)
{
    extern __shared__ __align__(128) char smem[];
    gemm_f16_body<0>(A, B, C, nullptr, 1.f, smem);
}

// =========================================================================
// Flash sliding-window attention, single-pass fp16; scores in log2 domain
// (Q pre-scaled by log2e) so softmax uses raw ex2.approx (1 MUFU, no FMUL).
// 8 warps x 16 query rows (BQ=128), cp.async double-buffered K/V, fp16 out.
// =========================================================================
#define LDA 72                         /* fp16 row stride: 144B */
#define SZ_Q  (128 * LDA * 2)          /* 18432 */
#define SZ_KV (64 * LDA * 2)           /* 9216  */
#define ATTN_SMEM (SZ_Q + 4 * SZ_KV)   /* 55296 */

__global__ __launch_bounds__(256, 2)
void attn_f16(const __half* __restrict__ Qc, const __half* __restrict__ Kc,
              const __half* __restrict__ Vc, __half* __restrict__ o)
{
    extern __shared__ __align__(128) char smem[];
    const uint32_t sQ  = smem_u32(smem);
    const uint32_t sK0 = sQ + SZ_Q;
    const uint32_t sV0 = sK0 + SZ_KV;
    const uint32_t sK1 = sV0 + SZ_KV;
    const uint32_t sV1 = sK1 + SZ_KV;

    const int b   = blockIdx.z;
    const int h   = blockIdx.y;
    const int q0  = blockIdx.x * 128;
    const int tid = threadIdx.x;
    const int lane = tid & 31;
    const int wid  = tid >> 5;
    const int wm   = wid * 16;

    const __half* qg = Qc + ((size_t)(b * NHEAD + h) * SEQ + q0) * 64;
    const __half* kg = Kc + ((size_t)(b * NHEAD + h) * SEQ) * 64;
    const __half* vg = Vc + ((size_t)(b * NHEAD + h) * SEQ) * 64;

    const int kstart = max(0, q0 - 256);
    const int ntiles = (q0 + 128 - kstart) >> 6;

    #pragma unroll
    for (int i = 0; i < 4; i++) {
        int idx = tid + i * 256;
        int row = idx >> 3;
        int c   = idx & 7;
        CP_ASYNC16(sQ + (uint32_t)(row * (LDA * 2) + c * 16),
                   qg + (size_t)row * 64 + c * 8);
    }
    #pragma unroll
    for (int i = 0; i < 2; i++) {
        int idx = tid + i * 256;
        int row = idx >> 3;
        int c   = idx & 7;
        CP_ASYNC16(sK0 + (uint32_t)(row * (LDA * 2) + c * 16),
                   kg + (size_t)(kstart + row) * 64 + c * 8);
        CP_ASYNC16(sV0 + (uint32_t)(row * (LDA * 2) + c * 16),
                   vg + (size_t)(kstart + row) * 64 + c * 8);
    }
    CP_COMMIT();

    const int g  = lane >> 2;
    const int t4 = lane & 3;
    const int arow  = ((lane >> 3) & 1) * 8 + (lane & 7);
    const int ahalf = (lane >> 4) * 8;
    const int brow  = ((lane >> 4) << 3) + (lane & 7);
    const int bhalf = ((lane >> 3) & 1) * 8;
    const int vrow  = (lane & 7) + ((lane >> 3) & 1) * 8;
    const int vcol  = (lane >> 4) * 8;

    CP_WAIT0();
    __syncthreads();

    uint32_t qf[4][4];
    #pragma unroll
    for (int j = 0; j < 4; j++)
        LDMATRIX_X4(qf[j][0], qf[j][1], qf[j][2], qf[j][3],
                    sQ + (uint32_t)(((wm + arow) * LDA + j * 16 + ahalf) * 2));

    float m0 = -1e30f, m1 = -1e30f, l0 = 0.f, l1 = 0.f;
    float of[8][4];
    #pragma unroll
    for (int i = 0; i < 8; i++)
        #pragma unroll
        for (int j = 0; j < 4; j++) of[i][j] = 0.f;

    const int qrow0 = q0 + wm + g;
    const int qrow1 = qrow0 + 8;

    for (int t = 0; t < ntiles; t++) {
        const int kb = kstart + t * 64;

        if (t + 1 < ntiles) {
            const uint32_t dK = ((t + 1) & 1) ? sK1 : sK0;
            const uint32_t dV = ((t + 1) & 1) ? sV1 : sV0;
            const int kn = kb + 64;
            #pragma unroll
            for (int i = 0; i < 2; i++) {
                int idx = tid + i * 256;
                int row = idx >> 3;
                int c   = idx & 7;
                CP_ASYNC16(dK + (uint32_t)(row * (LDA * 2) + c * 16),
                           kg + (size_t)(kn + row) * 64 + c * 8);
                CP_ASYNC16(dV + (uint32_t)(row * (LDA * 2) + c * 16),
                           vg + (size_t)(kn + row) * 64 + c * 8);
            }
            CP_COMMIT();
        }

        const uint32_t sK = (t & 1) ? sK1 : sK0;
        const uint32_t sV = (t & 1) ? sV1 : sV0;

        const bool active = (kb <= q0 + wm + 15) && (kb + 63 >= q0 + wm - (WIN - 1));

        if (active) {
            float sf[8][4];
            #pragma unroll
            for (int i = 0; i < 8; i++)
                #pragma unroll
                for (int j = 0; j < 4; j++) sf[i][j] = 0.f;

            #pragma unroll
            for (int j = 0; j < 4; j++) {
                #pragma unroll
                for (int np = 0; np < 4; np++) {
                    uint32_t r0, r1, r2, r3;
                    LDMATRIX_X4(r0, r1, r2, r3,
                                sK + (uint32_t)(((np * 16 + brow) * LDA + j * 16 + bhalf) * 2));
                    uint32_t b01[2] = {r0, r1}, b23[2] = {r2, r3};
                    MMAF16(sf[np * 2],     qf[j], b01);
                    MMAF16(sf[np * 2 + 1], qf[j], b23);
                }
            }

            const bool full = (kb + 63 <= q0 + wm) &&
                              (kb >= q0 + wm + 15 - (WIN - 1));
            if (!full) {
                #pragma unroll
                for (int nt = 0; nt < 8; nt++) {
                    int key0 = kb + nt * 8 + t4 * 2;
                    int key1 = key0 + 1;
                    if (!(key0 <= qrow0 && key0 >= qrow0 - (WIN - 1))) sf[nt][0] = -1e30f;
                    if (!(key1 <= qrow0 && key1 >= qrow0 - (WIN - 1))) sf[nt][1] = -1e30f;
                    if (!(key0 <= qrow1 && key0 >= qrow1 - (WIN - 1))) sf[nt][2] = -1e30f;
                    if (!(key1 <= qrow1 && key1 >= qrow1 - (WIN - 1))) sf[nt][3] = -1e30f;
                }
            }

            float tmax0 = -1e30f, tmax1 = -1e30f;
            #pragma unroll
            for (int nt = 0; nt < 8; nt++) {
                tmax0 = fmaxf(tmax0, fmaxf(sf[nt][0], sf[nt][1]));
                tmax1 = fmaxf(tmax1, fmaxf(sf[nt][2], sf[nt][3]));
            }
            tmax0 = fmaxf(tmax0, __shfl_xor_sync(0xffffffffu, tmax0, 1));
            tmax0 = fmaxf(tmax0, __shfl_xor_sync(0xffffffffu, tmax0, 2));
            tmax1 = fmaxf(tmax1, __shfl_xor_sync(0xffffffffu, tmax1, 1));
            tmax1 = fmaxf(tmax1, __shfl_xor_sync(0xffffffffu, tmax1, 2));

            float mn0 = fmaxf(m0, tmax0);
            float mn1 = fmaxf(m1, tmax1);
            float f0 = ex2(m0 - mn0);
            float f1 = ex2(m1 - mn1);
            l0 *= f0; l1 *= f1;
            #pragma unroll
            for (int nt = 0; nt < 8; nt++) {
                of[nt][0] *= f0; of[nt][1] *= f0;
                of[nt][2] *= f1; of[nt][3] *= f1;
            }

            uint32_t phi[8][2];
            #pragma unroll
            for (int nt = 0; nt < 8; nt++) {
                float p00 = ex2(sf[nt][0] - mn0);
                float p01 = ex2(sf[nt][1] - mn0);
                float p10 = ex2(sf[nt][2] - mn1);
                float p11 = ex2(sf[nt][3] - mn1);
                l0 += p00 + p01;
                l1 += p10 + p11;
                __half2 h0 = __floats2half2_rn(p00, p01);
                __half2 h1 = __floats2half2_rn(p10, p11);
                phi[nt][0] = *(uint32_t*)&h0;
                phi[nt][1] = *(uint32_t*)&h1;
            }
            m0 = mn0; m1 = mn1;

            #pragma unroll
            for (int kj = 0; kj < 4; kj++) {
                uint32_t aP[4] = { phi[2*kj][0], phi[2*kj][1],
                                   phi[2*kj+1][0], phi[2*kj+1][1] };
                #pragma unroll
                for (int np = 0; np < 4; np++) {
                    uint32_t r0, r1, r2, r3;
                    LDMATRIX_X4_T(r0, r1, r2, r3,
                        sV + (uint32_t)(((kj * 16 + vrow) * LDA + np * 16 + vcol) * 2));
                    uint32_t b01[2] = {r0, r1}, b23[2] = {r2, r3};
                    MMAF16(of[np * 2],     aP, b01);
                    MMAF16(of[np * 2 + 1], aP, b23);
                }
            }
        }

        if (t + 1 < ntiles) {
            CP_WAIT0();
            __syncthreads();
        }
    }

    l0 += __shfl_xor_sync(0xffffffffu, l0, 1);
    l0 += __shfl_xor_sync(0xffffffffu, l0, 2);
    l1 += __shfl_xor_sync(0xffffffffu, l1, 1);
    l1 += __shfl_xor_sync(0xffffffffu, l1, 2);
    float inv0 = 1.f / l0;
    float inv1 = 1.f / l1;

    __half* ob = o + (size_t)(b * SEQ + q0 + wm) * DMODEL + h * HDIM;
    #pragma unroll
    for (int nt = 0; nt < 8; nt++) {
        int col = nt * 8 + t4 * 2;
        __half2 v0 = __floats2half2_rn(of[nt][0] * inv0, of[nt][1] * inv0);
        __half2 v1 = __floats2half2_rn(of[nt][2] * inv1, of[nt][3] * inv1);
        *(__half2*)(ob + (size_t)g * DMODEL + col)       = v0;
        *(__half2*)(ob + (size_t)(g + 8) * DMODEL + col) = v1;
    }
}

// ---------------------------------------------------------------------------
extern "C" void kernel_launch(void* const* d_in, const int* in_sizes, int n_in,
                              void* d_out, int out_size)
{
    const float* x  = (const float*)d_in[0];
    const float* Wq = (const float*)d_in[1];
    const float* Wk = (const float*)d_in[2];
    const float* Wv = (const float*)d_in[3];
    const float* Wo = (const float*)d_in[4];
    float* out = (float*)d_out;

    __half *xh, *aoh, *wqh, *wkh, *wvh, *woh, *qs, *ks, *vs;
    cudaGetSymbolAddress((void**)&xh,  g_xh);
    cudaGetSymbolAddress((void**)&aoh, g_aoh);
    cudaGetSymbolAddress((void**)&wqh, g_wqh);
    cudaGetSymbolAddress((void**)&wkh, g_wkh);
    cudaGetSymbolAddress((void**)&wvh, g_wvh);
    cudaGetSymbolAddress((void**)&woh, g_woh);
    cudaGetSymbolAddress((void**)&qs,  g_qs);
    cudaGetSymbolAddress((void**)&ks,  g_ks);
    cudaGetSymbolAddress((void**)&vs,  g_vs);

    cudaFuncSetAttribute(gemm_qkv_f16, cudaFuncAttributeMaxDynamicSharedMemorySize,
                         SMEM_GEMM);
    cudaFuncSetAttribute(gemm_o_f16, cudaFuncAttributeMaxDynamicSharedMemorySize,
                         SMEM_GEMM);
    cudaFuncSetAttribute(attn_f16, cudaFuncAttributeMaxDynamicSharedMemorySize,
                         ATTN_SMEM);

    // 0: all input converts (x + 4 weights)
    conv_in_f16<<<MROWS + 4 * 1024, 256>>>(x, Wq, Wk, Wv, Wo,
                                           xh, wqh, wkh, wvh, woh);
    // 1: batched QKV projection, fused fp16 head-major epilogue (Q x log2e)
    gemm_qkv_f16<<<dim3(GN / 256, MROWS / 128, 3), 256, SMEM_GEMM>>>(
        xh, wqh, wkh, wvh, qs, ks, vs);
    // 2: attention, single-pass fp16, exp2-domain softmax
    attn_f16<<<dim3(SEQ / 128, NHEAD, BATCH), 256, ATTN_SMEM>>>(qs, ks, vs, aoh);
    // 3: output projection (profiled slot)
    gemm_o_f16<<<dim3(GN / 256, MROWS / 128), 256, SMEM_GEMM>>>(aoh, woh, out);
}